// round 3
// baseline (speedup 1.0000x reference)
#include <cuda_runtime.h>
#include <cuda_bf16.h>
#include <mma.h>

using namespace nvcuda;

// Problem constants
constexpr int kN  = 50000;
constexpr int kE  = 800000;
constexpr int kG  = 128;
constexpr int kD  = 128;
constexpr int kH  = 512;
constexpr int kH2 = 1024;
constexpr int kL  = 4;
#define BNS 0.9999950000374997f   // 1/sqrt(1+1e-5)

// ---------------- scratch (no cudaMalloc allowed) ----------------
__device__ float g_hv  [(size_t)kN * kH];
__device__ float g_zin [(size_t)kN * kH];
__device__ float g_y1  [(size_t)kN * kH2];
__device__ float g_h   [(size_t)kN * kH];
__device__ float g_vf  [kG * kH];
__device__ float g_pool[kG * kH];
__device__ float g_zv  [kG * kH2];
__device__ int   g_cnt [kG];

// ---------------- helpers ----------------
__device__ __forceinline__ float tf32_hi(float x) {
    return __uint_as_float(__float_as_uint(x) & 0xffffe000u);
}

// ---------------- GEMM: C = act((A@W + lb) * (ga*BNS) + be) ----------------
// A [M,K] row-major, W [K,Nc] row-major. 3xTF32 split for ~fp32 accuracy.
// CTA tile 128x128, BK=16, 8 warps (2x4), warp tile 64x32 (4x2 wmma 16x16x8).
template<int RELU>
__global__ void __launch_bounds__(256, 1) gemm_bn(
    const float* __restrict__ A, const float* __restrict__ W,
    const float* __restrict__ lb, const float* __restrict__ ga,
    const float* __restrict__ be, float* __restrict__ C,
    int M, int K, int Nc)
{
    __shared__ __align__(16) float sAh[128 * 20];
    __shared__ __align__(16) float sAl[128 * 20];
    __shared__ __align__(16) float sBh[16 * 132];
    __shared__ __align__(16) float sBl[16 * 132];

    const int tid  = threadIdx.x;
    const int warp = tid >> 5, lane = tid & 31;
    const int wm   = warp >> 2, wn = warp & 3;  // wm 0..1, wn 0..3
    const int bm0  = blockIdx.y * 128, bn0 = blockIdx.x * 128;

    wmma::fragment<wmma::accumulator, 16, 16, 8, float> acc[4][2];
#pragma unroll
    for (int i = 0; i < 4; i++)
#pragma unroll
        for (int j = 0; j < 2; j++) wmma::fill_fragment(acc[i][j], 0.0f);

    const int nK = K >> 4;
    for (int kt = 0; kt < nK; kt++) {
        const int k0 = kt << 4;
        // load A tile (128x16): 512 float4 by 256 threads
#pragma unroll
        for (int r = 0; r < 2; r++) {
            int t   = tid + (r << 8);
            int row = t >> 2;
            int c4  = (t & 3) << 2;
            float4 v = make_float4(0.f, 0.f, 0.f, 0.f);
            int gr = bm0 + row;
            if (gr < M) v = *reinterpret_cast<const float4*>(A + (size_t)gr * K + k0 + c4);
            float hx = tf32_hi(v.x), hy = tf32_hi(v.y), hz = tf32_hi(v.z), hw = tf32_hi(v.w);
            float* ph = &sAh[row * 20 + c4];
            float* pl = &sAl[row * 20 + c4];
            ph[0] = hx;        ph[1] = hy;        ph[2] = hz;        ph[3] = hw;
            pl[0] = v.x - hx;  pl[1] = v.y - hy;  pl[2] = v.z - hz;  pl[3] = v.w - hw;
        }
        // load B tile (16x128): 512 float4
#pragma unroll
        for (int r = 0; r < 2; r++) {
            int t   = tid + (r << 8);
            int row = t >> 5;
            int c4  = (t & 31) << 2;
            float4 v = *reinterpret_cast<const float4*>(W + (size_t)(k0 + row) * Nc + bn0 + c4);
            float hx = tf32_hi(v.x), hy = tf32_hi(v.y), hz = tf32_hi(v.z), hw = tf32_hi(v.w);
            float* ph = &sBh[row * 132 + c4];
            float* pl = &sBl[row * 132 + c4];
            ph[0] = hx;        ph[1] = hy;        ph[2] = hz;        ph[3] = hw;
            pl[0] = v.x - hx;  pl[1] = v.y - hy;  pl[2] = v.z - hz;  pl[3] = v.w - hw;
        }
        __syncthreads();
#pragma unroll
        for (int ks = 0; ks < 2; ks++) {
            const int kk = ks << 3;
            wmma::fragment<wmma::matrix_a, 16, 16, 8, wmma::precision::tf32, wmma::row_major> ah[4], al[4];
            wmma::fragment<wmma::matrix_b, 16, 16, 8, wmma::precision::tf32, wmma::row_major> bh[2], bl[2];
#pragma unroll
            for (int i = 0; i < 4; i++) {
                wmma::load_matrix_sync(ah[i], &sAh[(wm * 64 + i * 16) * 20 + kk], 20);
                wmma::load_matrix_sync(al[i], &sAl[(wm * 64 + i * 16) * 20 + kk], 20);
            }
#pragma unroll
            for (int j = 0; j < 2; j++) {
                wmma::load_matrix_sync(bh[j], &sBh[kk * 132 + wn * 32 + j * 16], 132);
                wmma::load_matrix_sync(bl[j], &sBl[kk * 132 + wn * 32 + j * 16], 132);
            }
#pragma unroll
            for (int i = 0; i < 4; i++)
#pragma unroll
                for (int j = 0; j < 2; j++) {
                    wmma::mma_sync(acc[i][j], ah[i], bh[j], acc[i][j]);
                    wmma::mma_sync(acc[i][j], al[i], bh[j], acc[i][j]);
                    wmma::mma_sync(acc[i][j], ah[i], bl[j], acc[i][j]);
                }
        }
        __syncthreads();
    }

    // epilogue: stage each 16x16 accumulator tile in smem (reuse sAh), then BN+bias+ReLU
    float* stage = &sAh[warp * 320];  // 16 rows * ld 20
#pragma unroll
    for (int i = 0; i < 4; i++)
#pragma unroll
        for (int j = 0; j < 2; j++) {
            __syncwarp();
            wmma::store_matrix_sync(stage, acc[i][j], 20, wmma::mem_row_major);
            __syncwarp();
#pragma unroll
            for (int t = lane; t < 256; t += 32) {
                int r  = t >> 4, c = t & 15;
                int gr = bm0 + wm * 64 + i * 16 + r;
                int gc = bn0 + wn * 32 + j * 16 + c;
                if (gr < M) {
                    float y = stage[r * 20 + c];
                    float s = ga[gc] * BNS;
                    float o = (y + lb[gc]) * s + be[gc];
                    if (RELU) o = fmaxf(o, 0.0f);
                    C[(size_t)gr * Nc + gc] = o;
                }
            }
        }
}

// ---------------- elementwise / graph kernels ----------------
__global__ void vinit_k(float* __restrict__ vf, const float* __restrict__ vemb) {
    int idx = blockIdx.x * blockDim.x + threadIdx.x;   // over G*H/4
    if (idx >= kG * kH / 4) return;
    reinterpret_cast<float4*>(vf)[idx] =
        reinterpret_cast<const float4*>(vemb)[idx & (kH / 4 - 1)];
}

__global__ void addvirt_k(const float* __restrict__ h, const int* __restrict__ batch,
                          const float* __restrict__ vf, float* __restrict__ out) {
    int idx = blockIdx.x * blockDim.x + threadIdx.x;   // over N*H/4
    if (idx >= kN * (kH / 4)) return;
    int n = idx >> 7;           // H/4 = 128
    int g = __ldg(batch + n);
    float4 a = reinterpret_cast<const float4*>(h)[idx];
    float4 b = reinterpret_cast<const float4*>(vf)[(g << 7) + (idx & 127)];
    a.x += b.x; a.y += b.y; a.z += b.z; a.w += b.w;
    reinterpret_cast<float4*>(out)[idx] = a;
}

template<int F>
__global__ void scatter_k(const float* __restrict__ feat, const int* __restrict__ src,
                          const int* __restrict__ dst, float* __restrict__ zin) {
    constexpr int C4 = F / 4;
    int idx = blockIdx.x * blockDim.x + threadIdx.x;   // over E*C4
    if (idx >= kE * C4) return;
    int e = idx / C4;
    int c = idx & (C4 - 1);
    int s = __ldg(src + e), d = __ldg(dst + e);
    float4 v = reinterpret_cast<const float4*>(feat)[(size_t)s * C4 + c];
    float* p = zin + (size_t)d * F + (c << 2);
    atomicAdd(p + 0, v.x);
    atomicAdd(p + 1, v.y);
    atomicAdd(p + 2, v.z);
    atomicAdd(p + 3, v.w);
}

__global__ void pooladd_k(const float* __restrict__ h, const int* __restrict__ batch,
                          float* __restrict__ pool) {
    int idx = blockIdx.x * blockDim.x + threadIdx.x;   // over N*H/4
    if (idx >= kN * (kH / 4)) return;
    int n = idx >> 7;
    int g = __ldg(batch + n);
    float4 v = reinterpret_cast<const float4*>(h)[idx];
    float* p = pool + (size_t)g * kH + ((idx & 127) << 2);
    atomicAdd(p + 0, v.x);
    atomicAdd(p + 1, v.y);
    atomicAdd(p + 2, v.z);
    atomicAdd(p + 3, v.w);
}

__global__ void count_k(const int* __restrict__ batch, int* __restrict__ cnt) {
    int n = blockIdx.x * blockDim.x + threadIdx.x;
    if (n < kN) atomicAdd(&cnt[__ldg(batch + n)], 1);
}

__global__ void div_k(float* __restrict__ out, const int* __restrict__ cnt) {
    int idx = blockIdx.x * blockDim.x + threadIdx.x;
    if (idx >= kG * kH) return;
    int g = idx >> 9;   // H = 512
    out[idx] /= fmaxf((float)cnt[g], 1.0f);
}

// ---------------- host launcher ----------------
static void run_gemm(const float* A, const float* W, const float* lb, const float* ga,
                     const float* be, float* C, int M, int K, int Nc, bool relu) {
    dim3 grid(Nc / 128, (M + 127) / 128);
    if (relu) gemm_bn<1><<<grid, 256>>>(A, W, lb, ga, be, C, M, K, Nc);
    else      gemm_bn<0><<<grid, 256>>>(A, W, lb, ga, be, C, M, K, Nc);
}

extern "C" void kernel_launch(void* const* d_in, const int* in_sizes, int n_in,
                              void* d_out, int out_size) {
    const float* x      = (const float*)d_in[0];
    const int*   ei     = (const int*)  d_in[1];
    const int*   batch  = (const int*)  d_in[2];
    const float* c1_W1  = (const float*)d_in[3];
    const float* c1_b1  = (const float*)d_in[4];
    const float* c1_g1  = (const float*)d_in[5];
    const float* c1_be1 = (const float*)d_in[6];
    const float* c1_W2  = (const float*)d_in[7];
    const float* c1_b2  = (const float*)d_in[8];
    const float* bn1_g  = (const float*)d_in[9];
    const float* bn1_b  = (const float*)d_in[10];
    const float* cs_W1  = (const float*)d_in[11];
    const float* cs_b1  = (const float*)d_in[12];
    const float* cs_g1  = (const float*)d_in[13];
    const float* cs_be1 = (const float*)d_in[14];
    const float* cs_W2  = (const float*)d_in[15];
    const float* cs_b2  = (const float*)d_in[16];
    const float* bns_g  = (const float*)d_in[17];
    const float* bns_b  = (const float*)d_in[18];
    const float* vemb   = (const float*)d_in[19];
    const float* v_W1   = (const float*)d_in[20];
    const float* v_b1   = (const float*)d_in[21];
    const float* v_g1   = (const float*)d_in[22];
    const float* v_be1  = (const float*)d_in[23];
    const float* v_W2   = (const float*)d_in[24];
    const float* v_b2   = (const float*)d_in[25];
    const float* v_g2   = (const float*)d_in[26];
    const float* v_be2  = (const float*)d_in[27];

    float *hv, *zin, *y1, *h, *vf, *pool, *zv;
    int* cnt;
    cudaGetSymbolAddress((void**)&hv,   g_hv);
    cudaGetSymbolAddress((void**)&zin,  g_zin);
    cudaGetSymbolAddress((void**)&y1,   g_y1);
    cudaGetSymbolAddress((void**)&h,    g_h);
    cudaGetSymbolAddress((void**)&vf,   g_vf);
    cudaGetSymbolAddress((void**)&pool, g_pool);
    cudaGetSymbolAddress((void**)&zv,   g_zv);
    cudaGetSymbolAddress((void**)&cnt,  g_cnt);

    const int* srcI = ei;
    const int* dstI = ei + kE;

    // virtual node features: broadcast vemb row
    vinit_k<<<(kG * kH / 4 + 255) / 256, 256>>>(vf, vemb);

    // ---- conv1: zin = x + scatter(x); MLP 128 -> 1024 -> 512 ----
    cudaMemcpyAsync(zin, x, (size_t)kN * kD * sizeof(float), cudaMemcpyDeviceToDevice);
    scatter_k<kD><<<(kE * (kD / 4) + 255) / 256, 256>>>(x, srcI, dstI, zin);
    run_gemm(zin, c1_W1, c1_b1, c1_g1, c1_be1, y1, kN, kD, kH2, true);
    run_gemm(y1, c1_W2, c1_b2, bn1_g, bn1_b, h, kN, kH2, kH, true);

    // ---- L GIN layers with virtual node ----
    for (int i = 0; i < kL; i++) {
        addvirt_k<<<(kN * (kH / 4) + 255) / 256, 256>>>(h, batch, vf, hv);
        cudaMemcpyAsync(zin, hv, (size_t)kN * kH * sizeof(float), cudaMemcpyDeviceToDevice);
        scatter_k<kH><<<(kE * (kH / 4) + 255) / 256, 256>>>(hv, srcI, dstI, zin);
        run_gemm(zin, cs_W1 + (size_t)i * kH * kH2, cs_b1 + i * kH2, cs_g1 + i * kH2,
                 cs_be1 + i * kH2, y1, kN, kH, kH2, true);
        run_gemm(y1, cs_W2 + (size_t)i * kH2 * kH, cs_b2 + i * kH, bns_g + i * kH,
                 bns_b + i * kH, h, kN, kH2, kH, i < kL - 1);
        if (i < kL - 1) {
            cudaMemcpyAsync(pool, vf, (size_t)kG * kH * sizeof(float), cudaMemcpyDeviceToDevice);
            pooladd_k<<<(kN * (kH / 4) + 255) / 256, 256>>>(h, batch, pool);
            run_gemm(pool, v_W1, v_b1, v_g1, v_be1, zv, kG, kH, kH2, true);
            run_gemm(zv, v_W2, v_b2, v_g2, v_be2, vf, kG, kH2, kH, true);
        }
    }

    // ---- mean-pool readout into d_out ----
    float* outp = (float*)d_out;
    cudaMemsetAsync(outp, 0, (size_t)kG * kH * sizeof(float));
    cudaMemsetAsync(cnt, 0, kG * sizeof(int));
    count_k<<<(kN + 255) / 256, 256>>>(batch, cnt);
    pooladd_k<<<(kN * (kH / 4) + 255) / 256, 256>>>(h, batch, outp);
    div_k<<<(kG * kH + 255) / 256, 256>>>(outp, cnt);
}

// round 8
// speedup vs baseline: 1.9900x; 1.9900x over previous
#include <cuda_runtime.h>
#include <cuda_bf16.h>
#include <mma.h>
#include <cstdint>

using namespace nvcuda;

// Problem constants
constexpr int kN  = 50000;
constexpr int kE  = 800000;
constexpr int kG  = 128;
constexpr int kD  = 128;
constexpr int kH  = 512;
constexpr int kH2 = 1024;
constexpr int kL  = 4;
#define BNS 0.9999950000374997f   // 1/sqrt(1+1e-5)

// ---------------- scratch (no cudaMalloc allowed) ----------------
__device__ float g_hv  [(size_t)kN * kH];
__device__ float g_zin [(size_t)kN * kH];
__device__ float g_y1  [(size_t)kN * kH2];
__device__ float g_h   [(size_t)kN * kH];
__device__ float g_vf  [kG * kH];
__device__ float g_pool[kG * kH];
__device__ float g_zv  [kG * kH2];
__device__ int   g_cnt [kG];

// Activation bf16 hi/lo split buffers (reused per GEMM)
__device__ __nv_bfloat16 g_ahi[(size_t)kN * kH2];
__device__ __nv_bfloat16 g_alo[(size_t)kN * kH2];
__device__ __nv_bfloat16 g_phi[kG * kH2];
__device__ __nv_bfloat16 g_plo[kG * kH2];

// Split weights, layout unchanged [K, Nc] row-major, bf16 hi/lo
constexpr size_t OFF_c1W1 = 0;                            // [128,1024]
constexpr size_t OFF_c1W2 = OFF_c1W1 + 128 * 1024;        // [1024,512]
constexpr size_t OFF_csW1 = OFF_c1W2 + 1024 * 512;        // 4 x [512,1024]
constexpr size_t OFF_csW2 = OFF_csW1 + 4ull * 512 * 1024; // 4 x [1024,512]
constexpr size_t OFF_vW1  = OFF_csW2 + 4ull * 1024 * 512; // [512,1024]
constexpr size_t OFF_vW2  = OFF_vW1 + 512 * 1024;         // [1024,512]
constexpr size_t WT_TOTAL = OFF_vW2 + 1024 * 512;
__device__ __nv_bfloat16 g_wthi[WT_TOTAL];
__device__ __nv_bfloat16 g_wtlo[WT_TOTAL];

// ---------------- helpers ----------------
__device__ __forceinline__ uint32_t smem_u32(const void* p) {
    uint32_t a;
    asm("{ .reg .u64 t; cvta.to.shared.u64 t, %1; cvt.u32.u64 %0, t; }" : "=r"(a) : "l"(p));
    return a;
}
__device__ __forceinline__ void cp16(uint32_t saddr, const void* gaddr) {
    asm volatile("cp.async.cg.shared.global [%0], [%1], 16;" :: "r"(saddr), "l"(gaddr) : "memory");
}
#define CP_COMMIT() asm volatile("cp.async.commit_group;" ::: "memory")
#define CP_WAIT(n)  asm volatile("cp.async.wait_group %0;" :: "n"(n) : "memory")

// ---------------- GEMM smem layout ----------------
constexpr int A_LD   = 40;                 // bf16 elems per A smem row (32 + 8 pad)
constexpr int B_LD   = 136;                // bf16 elems per B smem row (128 + 8 pad)
constexpr int A_BYT  = 128 * A_LD * 2;     // 10240
constexpr int B_BYT  = 32 * B_LD * 2;      // 8704
constexpr int ST_AH  = 0;
constexpr int ST_AL  = A_BYT;
constexpr int ST_BH  = 2 * A_BYT;
constexpr int ST_BL  = 2 * A_BYT + B_BYT;
constexpr int STAGE  = 2 * A_BYT + 2 * B_BYT;   // 37888
constexpr int OFF_SC = 2 * STAGE;               // 75776
constexpr int OFF_SH = OFF_SC + 512;
constexpr int DSMEM  = OFF_SH + 512;            // 76800

// ---------------- bf16-split GEMM: C = act((A@W + lb)*(ga*BNS) + be) ----------------
// Ahi/Alo [M,K] bf16 row-major, Bhi/Blo [K,Nc] bf16 row-major.
// CTA 128x128, BK=32, 8 warps (2x4), warp tile 64x32, wmma 16x16x16 bf16.
// 2-stage cp.async pipeline.
template<int RELU>
__global__ void __launch_bounds__(256, 1) gemm_bf16(
    const __nv_bfloat16* __restrict__ Ahi, const __nv_bfloat16* __restrict__ Alo,
    const __nv_bfloat16* __restrict__ Bhi, const __nv_bfloat16* __restrict__ Blo,
    const float* __restrict__ lb, const float* __restrict__ ga,
    const float* __restrict__ be, float* __restrict__ C,
    int M, int K, int Nc)
{
    extern __shared__ char sm[];
    const uint32_t sbase = smem_u32(sm);

    const int tid  = threadIdx.x;
    const int warp = tid >> 5, lane = tid & 31;
    const int wm   = warp >> 2, wn = warp & 3;
    const int bm0  = blockIdx.y * 128, bn0 = blockIdx.x * 128;

    // fused BN params for this column tile
    if (tid < 128) {
        float s = ga[bn0 + tid] * BNS;
        ((float*)(sm + OFF_SC))[tid] = s;
        ((float*)(sm + OFF_SH))[tid] = fmaf(lb[bn0 + tid], s, be[bn0 + tid]);
    }

    wmma::fragment<wmma::accumulator, 16, 16, 16, float> acc[4][2];
#pragma unroll
    for (int i = 0; i < 4; i++)
#pragma unroll
        for (int j = 0; j < 2; j++) wmma::fill_fragment(acc[i][j], 0.0f);

    const int nK = K >> 5;

    auto issue = [&](int c) {
        const int buf = c & 1;
        const int k0  = c << 5;
        const uint32_t sb = sbase + buf * STAGE;
        // A: 512 16B chunks per matrix, 2 per thread
#pragma unroll
        for (int t = 0; t < 2; t++) {
            int chunk = tid * 2 + t;
            int row   = chunk >> 2;
            int col8  = (chunk & 3) << 3;
            int gr    = bm0 + row;
            if (gr < M) {
                uint32_t off = (uint32_t)(row * A_LD + col8) * 2;
                size_t g = (size_t)gr * K + k0 + col8;
                cp16(sb + ST_AH + off, Ahi + g);
                cp16(sb + ST_AL + off, Alo + g);
            }
        }
        // B: 512 chunks per matrix, 2 per thread
#pragma unroll
        for (int t = 0; t < 2; t++) {
            int chunk = tid * 2 + t;
            int row   = chunk >> 4;
            int col8  = (chunk & 15) << 3;
            uint32_t off = (uint32_t)(row * B_LD + col8) * 2;
            size_t g = (size_t)(k0 + row) * Nc + bn0 + col8;
            cp16(sb + ST_BH + off, Bhi + g);
            cp16(sb + ST_BL + off, Blo + g);
        }
        CP_COMMIT();
    };

    issue(0);
    for (int c = 0; c < nK; c++) {
        if (c + 1 < nK) { issue(c + 1); CP_WAIT(1); }
        else            { CP_WAIT(0); }
        __syncthreads();

        const char* st = sm + (c & 1) * STAGE;
        const __nv_bfloat16* sAh = (const __nv_bfloat16*)(st + ST_AH);
        const __nv_bfloat16* sAl = (const __nv_bfloat16*)(st + ST_AL);
        const __nv_bfloat16* sBh = (const __nv_bfloat16*)(st + ST_BH);
        const __nv_bfloat16* sBl = (const __nv_bfloat16*)(st + ST_BL);
#pragma unroll
        for (int ks = 0; ks < 2; ks++) {
            const int kk = ks << 4;
            wmma::fragment<wmma::matrix_a, 16, 16, 16, __nv_bfloat16, wmma::row_major> ah[4], al[4];
            wmma::fragment<wmma::matrix_b, 16, 16, 16, __nv_bfloat16, wmma::row_major> bh[2], bl[2];
#pragma unroll
            for (int i = 0; i < 4; i++) {
                wmma::load_matrix_sync(ah[i], sAh + (wm * 64 + i * 16) * A_LD + kk, A_LD);
                wmma::load_matrix_sync(al[i], sAl + (wm * 64 + i * 16) * A_LD + kk, A_LD);
            }
#pragma unroll
            for (int j = 0; j < 2; j++) {
                wmma::load_matrix_sync(bh[j], sBh + kk * B_LD + wn * 32 + j * 16, B_LD);
                wmma::load_matrix_sync(bl[j], sBl + kk * B_LD + wn * 32 + j * 16, B_LD);
            }
#pragma unroll
            for (int i = 0; i < 4; i++)
#pragma unroll
                for (int j = 0; j < 2; j++) {
                    wmma::mma_sync(acc[i][j], ah[i], bh[j], acc[i][j]);
                    wmma::mma_sync(acc[i][j], ah[i], bl[j], acc[i][j]);
                    wmma::mma_sync(acc[i][j], al[i], bh[j], acc[i][j]);
                }
        }
        __syncthreads();
    }

    // epilogue: stage 16x16 tiles through smem, fuse BN/bias/ReLU
    float* stage = (float*)(sm + warp * 1280);   // 16 rows * ld 20 floats
    const float* sc = (const float*)(sm + OFF_SC);
    const float* sh = (const float*)(sm + OFF_SH);
#pragma unroll
    for (int i = 0; i < 4; i++)
#pragma unroll
        for (int j = 0; j < 2; j++) {
            __syncwarp();
            wmma::store_matrix_sync(stage, acc[i][j], 20, wmma::mem_row_major);
            __syncwarp();
#pragma unroll
            for (int t = lane; t < 256; t += 32) {
                int r  = t >> 4, cc = t & 15;
                int gr = bm0 + wm * 64 + i * 16 + r;
                int gc = bn0 + wn * 32 + j * 16 + cc;
                if (gr < M) {
                    float o = fmaf(stage[r * 20 + cc], sc[gc - bn0], sh[gc - bn0]);
                    if (RELU) o = fmaxf(o, 0.0f);
                    C[(size_t)gr * Nc + gc] = o;
                }
            }
        }
}

// ---------------- fp32 -> bf16 hi/lo split (elementwise, vectorized) ----------------
__global__ void split_k(const float* __restrict__ A, __nv_bfloat16* __restrict__ hi,
                        __nv_bfloat16* __restrict__ lo, int n4) {
    int i = blockIdx.x * blockDim.x + threadIdx.x;
    if (i >= n4) return;
    float4 v = reinterpret_cast<const float4*>(A)[i];
    unsigned short hx = __bfloat16_as_ushort(__float2bfloat16(v.x));
    unsigned short hy = __bfloat16_as_ushort(__float2bfloat16(v.y));
    unsigned short hz = __bfloat16_as_ushort(__float2bfloat16(v.z));
    unsigned short hw = __bfloat16_as_ushort(__float2bfloat16(v.w));
    float fx = __bfloat162float(__ushort_as_bfloat16(hx));
    float fy = __bfloat162float(__ushort_as_bfloat16(hy));
    float fz = __bfloat162float(__ushort_as_bfloat16(hz));
    float fw = __bfloat162float(__ushort_as_bfloat16(hw));
    unsigned short lx = __bfloat16_as_ushort(__float2bfloat16(v.x - fx));
    unsigned short ly = __bfloat16_as_ushort(__float2bfloat16(v.y - fy));
    unsigned short lz = __bfloat16_as_ushort(__float2bfloat16(v.z - fz));
    unsigned short lw = __bfloat16_as_ushort(__float2bfloat16(v.w - fw));
    uint2 uh, ul;
    uh.x = (uint32_t)hx | ((uint32_t)hy << 16);
    uh.y = (uint32_t)hz | ((uint32_t)hw << 16);
    ul.x = (uint32_t)lx | ((uint32_t)ly << 16);
    ul.y = (uint32_t)lz | ((uint32_t)lw << 16);
    reinterpret_cast<uint2*>(hi)[i] = uh;
    reinterpret_cast<uint2*>(lo)[i] = ul;
}

// ---------------- elementwise / graph kernels ----------------
__global__ void vinit_k(float* __restrict__ vf, const float* __restrict__ vemb) {
    int idx = blockIdx.x * blockDim.x + threadIdx.x;
    if (idx >= kG * kH / 4) return;
    reinterpret_cast<float4*>(vf)[idx] =
        reinterpret_cast<const float4*>(vemb)[idx & (kH / 4 - 1)];
}

__global__ void addvirt_k(const float* __restrict__ h, const int* __restrict__ batch,
                          const float* __restrict__ vf, float* __restrict__ out) {
    int idx = blockIdx.x * blockDim.x + threadIdx.x;
    if (idx >= kN * (kH / 4)) return;
    int n = idx >> 7;
    int g = __ldg(batch + n);
    float4 a = reinterpret_cast<const float4*>(h)[idx];
    float4 b = reinterpret_cast<const float4*>(vf)[(g << 7) + (idx & 127)];
    a.x += b.x; a.y += b.y; a.z += b.z; a.w += b.w;
    reinterpret_cast<float4*>(out)[idx] = a;
}

template<int F>
__global__ void scatter_k(const float* __restrict__ feat, const int* __restrict__ src,
                          const int* __restrict__ dst, float* __restrict__ zin) {
    constexpr int C4 = F / 4;
    int idx = blockIdx.x * blockDim.x + threadIdx.x;
    if (idx >= kE * C4) return;
    int e = idx / C4;
    int c = idx & (C4 - 1);
    int s = __ldg(src + e), d = __ldg(dst + e);
    float4 v = reinterpret_cast<const float4*>(feat)[(size_t)s * C4 + c];
    float* p = zin + (size_t)d * F + (c << 2);
    atomicAdd(p + 0, v.x);
    atomicAdd(p + 1, v.y);
    atomicAdd(p + 2, v.z);
    atomicAdd(p + 3, v.w);
}

__global__ void pooladd_k(const float* __restrict__ h, const int* __restrict__ batch,
                          float* __restrict__ pool) {
    int idx = blockIdx.x * blockDim.x + threadIdx.x;
    if (idx >= kN * (kH / 4)) return;
    int n = idx >> 7;
    int g = __ldg(batch + n);
    float4 v = reinterpret_cast<const float4*>(h)[idx];
    float* p = pool + (size_t)g * kH + ((idx & 127) << 2);
    atomicAdd(p + 0, v.x);
    atomicAdd(p + 1, v.y);
    atomicAdd(p + 2, v.z);
    atomicAdd(p + 3, v.w);
}

__global__ void count_k(const int* __restrict__ batch, int* __restrict__ cnt) {
    int n = blockIdx.x * blockDim.x + threadIdx.x;
    if (n < kN) atomicAdd(&cnt[__ldg(batch + n)], 1);
}

__global__ void div_k(float* __restrict__ out, const int* __restrict__ cnt) {
    int idx = blockIdx.x * blockDim.x + threadIdx.x;
    if (idx >= kG * kH) return;
    int g = idx >> 9;
    out[idx] /= fmaxf((float)cnt[g], 1.0f);
}

// ---------------- host launcher ----------------
static void run_gemm(const __nv_bfloat16* Ahi, const __nv_bfloat16* Alo,
                     const __nv_bfloat16* Bhi, const __nv_bfloat16* Blo,
                     const float* lb, const float* ga, const float* be, float* C,
                     int M, int K, int Nc, bool relu) {
    dim3 grid(Nc / 128, (M + 127) / 128);
    if (relu) gemm_bf16<1><<<grid, 256, DSMEM>>>(Ahi, Alo, Bhi, Blo, lb, ga, be, C, M, K, Nc);
    else      gemm_bf16<0><<<grid, 256, DSMEM>>>(Ahi, Alo, Bhi, Blo, lb, ga, be, C, M, K, Nc);
}

static void run_split(const float* A, __nv_bfloat16* hi, __nv_bfloat16* lo, size_t n) {
    int n4 = (int)(n / 4);
    split_k<<<(n4 + 255) / 256, 256>>>(A, hi, lo, n4);
}

extern "C" void kernel_launch(void* const* d_in, const int* in_sizes, int n_in,
                              void* d_out, int out_size) {
    const float* x      = (const float*)d_in[0];
    const int*   ei     = (const int*)  d_in[1];
    const int*   batch  = (const int*)  d_in[2];
    const float* c1_W1  = (const float*)d_in[3];
    const float* c1_b1  = (const float*)d_in[4];
    const float* c1_g1  = (const float*)d_in[5];
    const float* c1_be1 = (const float*)d_in[6];
    const float* c1_W2  = (const float*)d_in[7];
    const float* c1_b2  = (const float*)d_in[8];
    const float* bn1_g  = (const float*)d_in[9];
    const float* bn1_b  = (const float*)d_in[10];
    const float* cs_W1  = (const float*)d_in[11];
    const float* cs_b1  = (const float*)d_in[12];
    const float* cs_g1  = (const float*)d_in[13];
    const float* cs_be1 = (const float*)d_in[14];
    const float* cs_W2  = (const float*)d_in[15];
    const float* cs_b2  = (const float*)d_in[16];
    const float* bns_g  = (const float*)d_in[17];
    const float* bns_b  = (const float*)d_in[18];
    const float* vemb   = (const float*)d_in[19];
    const float* v_W1   = (const float*)d_in[20];
    const float* v_b1   = (const float*)d_in[21];
    const float* v_g1   = (const float*)d_in[22];
    const float* v_be1  = (const float*)d_in[23];
    const float* v_W2   = (const float*)d_in[24];
    const float* v_b2   = (const float*)d_in[25];
    const float* v_g2   = (const float*)d_in[26];
    const float* v_be2  = (const float*)d_in[27];

    cudaFuncSetAttribute(gemm_bf16<0>, cudaFuncAttributeMaxDynamicSharedMemorySize, DSMEM);
    cudaFuncSetAttribute(gemm_bf16<1>, cudaFuncAttributeMaxDynamicSharedMemorySize, DSMEM);

    float *hv, *zin, *y1, *h, *vf, *pool, *zv;
    int* cnt;
    __nv_bfloat16 *wthi, *wtlo, *ahi, *alo, *phi, *plo;
    cudaGetSymbolAddress((void**)&hv,   g_hv);
    cudaGetSymbolAddress((void**)&zin,  g_zin);
    cudaGetSymbolAddress((void**)&y1,   g_y1);
    cudaGetSymbolAddress((void**)&h,    g_h);
    cudaGetSymbolAddress((void**)&vf,   g_vf);
    cudaGetSymbolAddress((void**)&pool, g_pool);
    cudaGetSymbolAddress((void**)&zv,   g_zv);
    cudaGetSymbolAddress((void**)&cnt,  g_cnt);
    cudaGetSymbolAddress((void**)&wthi, g_wthi);
    cudaGetSymbolAddress((void**)&wtlo, g_wtlo);
    cudaGetSymbolAddress((void**)&ahi,  g_ahi);
    cudaGetSymbolAddress((void**)&alo,  g_alo);
    cudaGetSymbolAddress((void**)&phi,  g_phi);
    cudaGetSymbolAddress((void**)&plo,  g_plo);

    const int* srcI = ei;
    const int* dstI = ei + kE;

    // ---- weight splits (elementwise, layout preserved [K,Nc]) ----
    run_split(c1_W1, wthi + OFF_c1W1, wtlo + OFF_c1W1, (size_t)kD * kH2);
    run_split(c1_W2, wthi + OFF_c1W2, wtlo + OFF_c1W2, (size_t)kH2 * kH);
    for (int i = 0; i < kL; i++) {
        run_split(cs_W1 + (size_t)i * kH * kH2,
                  wthi + OFF_csW1 + (size_t)i * kH * kH2,
                  wtlo + OFF_csW1 + (size_t)i * kH * kH2, (size_t)kH * kH2);
        run_split(cs_W2 + (size_t)i * kH2 * kH,
                  wthi + OFF_csW2 + (size_t)i * kH2 * kH,
                  wtlo + OFF_csW2 + (size_t)i * kH2 * kH, (size_t)kH2 * kH);
    }
    run_split(v_W1, wthi + OFF_vW1, wtlo + OFF_vW1, (size_t)kH * kH2);
    run_split(v_W2, wthi + OFF_vW2, wtlo + OFF_vW2, (size_t)kH2 * kH);

    // virtual node features
    vinit_k<<<(kG * kH / 4 + 255) / 256, 256>>>(vf, vemb);

    // ---- conv1: zin = x + scatter(x); MLP 128 -> 1024 -> 512 ----
    cudaMemcpyAsync(zin, x, (size_t)kN * kD * sizeof(float), cudaMemcpyDeviceToDevice);
    scatter_k<kD><<<(kE * (kD / 4) + 255) / 256, 256>>>(x, srcI, dstI, zin);
    run_split(zin, ahi, alo, (size_t)kN * kD);
    run_gemm(ahi, alo, wthi + OFF_c1W1, wtlo + OFF_c1W1, c1_b1, c1_g1, c1_be1, y1, kN, kD, kH2, true);
    run_split(y1, ahi, alo, (size_t)kN * kH2);
    run_gemm(ahi, alo, wthi + OFF_c1W2, wtlo + OFF_c1W2, c1_b2, bn1_g, bn1_b, h, kN, kH2, kH, true);

    // ---- L GIN layers with virtual node ----
    for (int i = 0; i < kL; i++) {
        addvirt_k<<<(kN * (kH / 4) + 255) / 256, 256>>>(h, batch, vf, hv);
        cudaMemcpyAsync(zin, hv, (size_t)kN * kH * sizeof(float), cudaMemcpyDeviceToDevice);
        scatter_k<kH><<<(kE * (kH / 4) + 255) / 256, 256>>>(hv, srcI, dstI, zin);
        run_split(zin, ahi, alo, (size_t)kN * kH);
        run_gemm(ahi, alo, wthi + OFF_csW1 + (size_t)i * kH * kH2,
                 wtlo + OFF_csW1 + (size_t)i * kH * kH2,
                 cs_b1 + i * kH2, cs_g1 + i * kH2, cs_be1 + i * kH2, y1, kN, kH, kH2, true);
        run_split(y1, ahi, alo, (size_t)kN * kH2);
        run_gemm(ahi, alo, wthi + OFF_csW2 + (size_t)i * kH2 * kH,
                 wtlo + OFF_csW2 + (size_t)i * kH2 * kH,
                 cs_b2 + i * kH, bns_g + i * kH, bns_b + i * kH, h, kN, kH2, kH, i < kL - 1);
        if (i < kL - 1) {
            cudaMemcpyAsync(pool, vf, (size_t)kG * kH * sizeof(float), cudaMemcpyDeviceToDevice);
            pooladd_k<<<(kN * (kH / 4) + 255) / 256, 256>>>(h, batch, pool);
            run_split(pool, phi, plo, (size_t)kG * kH);
            run_gemm(phi, plo, wthi + OFF_vW1, wtlo + OFF_vW1, v_b1, v_g1, v_be1, zv, kG, kH, kH2, true);
            run_split(zv, phi, plo, (size_t)kG * kH2);
            run_gemm(phi, plo, wthi + OFF_vW2, wtlo + OFF_vW2, v_b2, v_g2, v_be2, vf, kG, kH2, kH, true);
        }
    }

    // ---- mean-pool readout into d_out ----
    float* outp = (float*)d_out;
    cudaMemsetAsync(outp, 0, (size_t)kG * kH * sizeof(float));
    cudaMemsetAsync(cnt, 0, kG * sizeof(int));
    count_k<<<(kN + 255) / 256, 256>>>(batch, cnt);
    pooladd_k<<<(kN * (kH / 4) + 255) / 256, 256>>>(h, batch, outp);
    div_k<<<(kG * kH + 255) / 256, 256>>>(outp, cnt);
}

// round 9
// speedup vs baseline: 3.3072x; 1.6619x over previous
#include <cuda_runtime.h>
#include <cuda_bf16.h>
#include <mma.h>
#include <cstdint>

using namespace nvcuda;

// Problem constants
constexpr int kN  = 50000;
constexpr int kE  = 800000;
constexpr int kG  = 128;
constexpr int kD  = 128;
constexpr int kH  = 512;
constexpr int kH2 = 1024;
constexpr int kL  = 4;
#define BNS 0.9999950000374997f   // 1/sqrt(1+1e-5)

// ---------------- scratch (no cudaMalloc allowed) ----------------
__device__ float g_hv  [(size_t)kN * kH];
__device__ float g_zin [(size_t)kN * kH];
__device__ float g_h   [(size_t)kN * kH];
__device__ float g_vf  [kG * kH];
__device__ float g_pool[kG * kH];
__device__ int   g_cnt [kG];

// CSR structures
__device__ int g_deg   [kN];
__device__ int g_cur   [kN];
__device__ int g_rowptr[kN + 1];
__device__ int g_esrc  [kE];

// bf16 split buffers
__device__ __nv_bfloat16 g_ahi[(size_t)kN * kH];   // split of zin (GEMM1 input)
__device__ __nv_bfloat16 g_alo[(size_t)kN * kH];
__device__ __nv_bfloat16 g_bhi[(size_t)kN * kH2];  // GEMM1 output (y1 split)
__device__ __nv_bfloat16 g_blo[(size_t)kN * kH2];
__device__ __nv_bfloat16 g_phi[kG * kH];           // pool split
__device__ __nv_bfloat16 g_plo[kG * kH];
__device__ __nv_bfloat16 g_qhi[kG * kH2];          // zv split
__device__ __nv_bfloat16 g_qlo[kG * kH2];

// Split weights, layout [K, Nc] row-major, bf16 hi/lo
constexpr size_t OFF_c1W1 = 0;                            // [128,1024]
constexpr size_t OFF_c1W2 = OFF_c1W1 + 128 * 1024;        // [1024,512]
constexpr size_t OFF_csW1 = OFF_c1W2 + 1024 * 512;        // 4 x [512,1024]
constexpr size_t OFF_csW2 = OFF_csW1 + 4ull * 512 * 1024; // 4 x [1024,512]
constexpr size_t OFF_vW1  = OFF_csW2 + 4ull * 1024 * 512; // [512,1024]
constexpr size_t OFF_vW2  = OFF_vW1 + 512 * 1024;         // [1024,512]
constexpr size_t WT_TOTAL = OFF_vW2 + 1024 * 512;
__device__ __nv_bfloat16 g_wthi[WT_TOTAL];
__device__ __nv_bfloat16 g_wtlo[WT_TOTAL];

// ---------------- helpers ----------------
__device__ __forceinline__ uint32_t smem_u32(const void* p) {
    uint32_t a;
    asm("{ .reg .u64 t; cvta.to.shared.u64 t, %1; cvt.u32.u64 %0, t; }" : "=r"(a) : "l"(p));
    return a;
}
__device__ __forceinline__ void cp16(uint32_t saddr, const void* gaddr) {
    asm volatile("cp.async.cg.shared.global [%0], [%1], 16;" :: "r"(saddr), "l"(gaddr) : "memory");
}
#define CP_COMMIT() asm volatile("cp.async.commit_group;" ::: "memory")
#define CP_WAIT(n)  asm volatile("cp.async.wait_group %0;" :: "n"(n) : "memory")

// ---------------- GEMM smem layout (tile 128x256, BK=32, 3 stages) ----------------
constexpr int A_LD   = 40;                  // 32 + 8 pad
constexpr int B_LD   = 264;                 // 256 + 8 pad
constexpr int A_MATB = 128 * A_LD * 2;      // 10240 bytes per A matrix (hi or lo)
constexpr int B_MATB = 32 * B_LD * 2;       // 16896 bytes per B matrix
constexpr int ST_AH  = 0;
constexpr int ST_AL  = A_MATB;              // 10240
constexpr int ST_BH  = 2 * A_MATB;          // 20480
constexpr int ST_BL  = 2 * A_MATB + B_MATB; // 37376
constexpr int STAGE  = 2 * A_MATB + 2 * B_MATB; // 54272
constexpr int NSTG   = 3;
constexpr int OFF_SC = NSTG * STAGE;        // 162816
constexpr int OFF_SH = OFF_SC + 1024;
constexpr int DSMEM  = OFF_SH + 1024;       // 164864

// ---------------- bf16-split GEMM: out = act((A@W + lb)*(ga*BNS) + be) ----------------
// Ahi/Alo [M,K] bf16 row-major; Bhi/Blo [K,Nc] bf16 row-major.
// CTA 128x256, 8 warps (2x4), warp tile 64x64, wmma 16x16x16, 3-term split.
// SPLIT=1: write bf16 hi/lo outputs; SPLIT=0: write fp32.
template<int RELU, int SPLIT>
__global__ void __launch_bounds__(256, 1) gemm_bf16(
    const __nv_bfloat16* __restrict__ Ahi, const __nv_bfloat16* __restrict__ Alo,
    const __nv_bfloat16* __restrict__ Bhi, const __nv_bfloat16* __restrict__ Blo,
    const float* __restrict__ lb, const float* __restrict__ ga,
    const float* __restrict__ be, float* __restrict__ C,
    __nv_bfloat16* __restrict__ Chi, __nv_bfloat16* __restrict__ Clo,
    int M, int K, int Nc)
{
    extern __shared__ char sm[];
    const uint32_t sbase = smem_u32(sm);

    const int tid  = threadIdx.x;
    const int warp = tid >> 5, lane = tid & 31;
    const int wm   = warp >> 2, wn = warp & 3;
    const int bm0  = blockIdx.y * 128, bn0 = blockIdx.x * 256;

    // fused BN params for this 256-column tile
    {
        float s = ga[bn0 + tid] * BNS;
        ((float*)(sm + OFF_SC))[tid] = s;
        ((float*)(sm + OFF_SH))[tid] = fmaf(lb[bn0 + tid], s, be[bn0 + tid]);
    }

    wmma::fragment<wmma::accumulator, 16, 16, 16, float> acc[4][4];
#pragma unroll
    for (int i = 0; i < 4; i++)
#pragma unroll
        for (int j = 0; j < 4; j++) wmma::fill_fragment(acc[i][j], 0.0f);

    const int nK = K >> 5;

    auto issue = [&](int c) {
        const int buf = c % NSTG;
        const int k0  = c << 5;
        const uint32_t sb = sbase + buf * STAGE;
        // A: 512 chunks of 16B per matrix (128 rows x 32 cols bf16)
#pragma unroll
        for (int t = 0; t < 2; t++) {
            int chunk = tid + (t << 8);
            int row   = chunk >> 2;
            int col8  = (chunk & 3) << 3;
            int gr    = bm0 + row;
            if (gr < M) {
                uint32_t off = (uint32_t)(row * A_LD + col8) * 2;
                size_t g = (size_t)gr * K + k0 + col8;
                cp16(sb + ST_AH + off, Ahi + g);
                cp16(sb + ST_AL + off, Alo + g);
            }
        }
        // B: 1024 chunks per matrix (32 rows x 256 cols bf16)
#pragma unroll
        for (int t = 0; t < 4; t++) {
            int chunk = tid + (t << 8);
            int row   = chunk >> 5;
            int col8  = (chunk & 31) << 3;
            uint32_t off = (uint32_t)(row * B_LD + col8) * 2;
            size_t g = (size_t)(k0 + row) * Nc + bn0 + col8;
            cp16(sb + ST_BH + off, Bhi + g);
            cp16(sb + ST_BL + off, Blo + g);
        }
        CP_COMMIT();
    };

    issue(0);
    if (nK > 1) issue(1);
    for (int c = 0; c < nK; c++) {
        if (c == nK - 1) { CP_WAIT(0); }
        else             { CP_WAIT(1); }
        __syncthreads();
        if (c + 2 < nK) issue(c + 2);

        const char* st = sm + (c % NSTG) * STAGE;
        const __nv_bfloat16* sAh = (const __nv_bfloat16*)(st + ST_AH);
        const __nv_bfloat16* sAl = (const __nv_bfloat16*)(st + ST_AL);
        const __nv_bfloat16* sBh = (const __nv_bfloat16*)(st + ST_BH);
        const __nv_bfloat16* sBl = (const __nv_bfloat16*)(st + ST_BL);
#pragma unroll
        for (int ks = 0; ks < 2; ks++) {
            const int kk = ks << 4;
            wmma::fragment<wmma::matrix_a, 16, 16, 16, __nv_bfloat16, wmma::row_major> ah[4], al[4];
#pragma unroll
            for (int i = 0; i < 4; i++) {
                wmma::load_matrix_sync(ah[i], sAh + (wm * 64 + i * 16) * A_LD + kk, A_LD);
                wmma::load_matrix_sync(al[i], sAl + (wm * 64 + i * 16) * A_LD + kk, A_LD);
            }
#pragma unroll
            for (int j = 0; j < 4; j++) {
                wmma::fragment<wmma::matrix_b, 16, 16, 16, __nv_bfloat16, wmma::row_major> bh, bl;
                wmma::load_matrix_sync(bh, sBh + kk * B_LD + wn * 64 + j * 16, B_LD);
                wmma::load_matrix_sync(bl, sBl + kk * B_LD + wn * 64 + j * 16, B_LD);
#pragma unroll
                for (int i = 0; i < 4; i++) {
                    wmma::mma_sync(acc[i][j], ah[i], bh, acc[i][j]);
                    wmma::mma_sync(acc[i][j], ah[i], bl, acc[i][j]);
                    wmma::mma_sync(acc[i][j], al[i], bh, acc[i][j]);
                }
            }
        }
        __syncthreads();
    }

    // epilogue: stage 16x16 tiles via smem, fused BN/bias/ReLU (+optional split)
    float* stage = (float*)(sm + warp * 1280);   // 16 rows * ld 20
    const float* sc = (const float*)(sm + OFF_SC);
    const float* sh = (const float*)(sm + OFF_SH);
#pragma unroll
    for (int i = 0; i < 4; i++)
#pragma unroll
        for (int j = 0; j < 4; j++) {
            __syncwarp();
            wmma::store_matrix_sync(stage, acc[i][j], 20, wmma::mem_row_major);
            __syncwarp();
#pragma unroll
            for (int t = lane; t < 256; t += 32) {
                int r   = t >> 4, cc = t & 15;
                int gr  = bm0 + wm * 64 + i * 16 + r;
                int gcl = wn * 64 + j * 16 + cc;
                if (gr < M) {
                    float o = fmaf(stage[r * 20 + cc], sc[gcl], sh[gcl]);
                    if (RELU) o = fmaxf(o, 0.0f);
                    size_t idx = (size_t)gr * Nc + bn0 + gcl;
                    if (SPLIT) {
                        __nv_bfloat16 hi = __float2bfloat16(o);
                        Chi[idx] = hi;
                        Clo[idx] = __float2bfloat16(o - __bfloat162float(hi));
                    } else {
                        C[idx] = o;
                    }
                }
            }
        }
}

// ---------------- fp32 -> bf16 hi/lo split ----------------
__global__ void split_k(const float* __restrict__ A, __nv_bfloat16* __restrict__ hi,
                        __nv_bfloat16* __restrict__ lo, int n4) {
    int i = blockIdx.x * blockDim.x + threadIdx.x;
    if (i >= n4) return;
    float4 v = reinterpret_cast<const float4*>(A)[i];
    unsigned short hx = __bfloat16_as_ushort(__float2bfloat16(v.x));
    unsigned short hy = __bfloat16_as_ushort(__float2bfloat16(v.y));
    unsigned short hz = __bfloat16_as_ushort(__float2bfloat16(v.z));
    unsigned short hw = __bfloat16_as_ushort(__float2bfloat16(v.w));
    float fx = __bfloat162float(__ushort_as_bfloat16(hx));
    float fy = __bfloat162float(__ushort_as_bfloat16(hy));
    float fz = __bfloat162float(__ushort_as_bfloat16(hz));
    float fw = __bfloat162float(__ushort_as_bfloat16(hw));
    unsigned short lx = __bfloat16_as_ushort(__float2bfloat16(v.x - fx));
    unsigned short ly = __bfloat16_as_ushort(__float2bfloat16(v.y - fy));
    unsigned short lz = __bfloat16_as_ushort(__float2bfloat16(v.z - fz));
    unsigned short lw = __bfloat16_as_ushort(__float2bfloat16(v.w - fw));
    uint2 uh, ul;
    uh.x = (uint32_t)hx | ((uint32_t)hy << 16);
    uh.y = (uint32_t)hz | ((uint32_t)hw << 16);
    ul.x = (uint32_t)lx | ((uint32_t)ly << 16);
    ul.y = (uint32_t)lz | ((uint32_t)lw << 16);
    reinterpret_cast<uint2*>(hi)[i] = uh;
    reinterpret_cast<uint2*>(lo)[i] = ul;
}

// ---------------- CSR build ----------------
__global__ void degcount_k(const int* __restrict__ dst, int* __restrict__ deg) {
    int e = blockIdx.x * blockDim.x + threadIdx.x;
    if (e < kE) atomicAdd(&deg[__ldg(dst + e)], 1);
}

__global__ void scan_k(const int* __restrict__ deg, int* __restrict__ rowptr) {
    __shared__ int part[1024];
    __shared__ int total;
    const int t  = threadIdx.x;
    const int CH = (kN + 1023) / 1024;   // 49
    int start = t * CH;
    int end   = start + CH; if (end > kN) end = kN;
    int s = 0;
    for (int i = start; i < end; i++) s += deg[i];
    part[t] = s;
    __syncthreads();
    if (t == 0) {
        int run = 0;
        for (int j = 0; j < 1024; j++) { int v = part[j]; part[j] = run; run += v; }
        total = run;
    }
    __syncthreads();
    int run = part[t];
    for (int i = start; i < end; i++) { rowptr[i] = run; run += deg[i]; }
    if (t == 0) rowptr[kN] = total;
}

__global__ void fill_k(const int* __restrict__ src, const int* __restrict__ dst,
                       const int* __restrict__ rowptr, int* __restrict__ cur,
                       int* __restrict__ esrc) {
    int e = blockIdx.x * blockDim.x + threadIdx.x;
    if (e >= kE) return;
    int d = __ldg(dst + e);
    int pos = rowptr[d] + atomicAdd(&cur[d], 1);
    esrc[pos] = __ldg(src + e);
}

// ---------------- CSR gather aggregation: zin[n] = feat[n] + sum_{s in N(n)} feat[s] ----------------
template<int F>
__global__ void aggregate_k(const float* __restrict__ feat,
                            const int* __restrict__ rowptr, const int* __restrict__ esrc,
                            float* __restrict__ zin) {
    constexpr int C4 = F / 4;
    const int n = blockIdx.x;
    const int c = threadIdx.x;   // 0..C4-1
    const float4* f4 = reinterpret_cast<const float4*>(feat);
    float4 acc = f4[(size_t)n * C4 + c];
    const int p0 = __ldg(rowptr + n), p1 = __ldg(rowptr + n + 1);
    for (int p = p0; p < p1; p++) {
        int s = __ldg(esrc + p);
        float4 v = f4[(size_t)s * C4 + c];
        acc.x += v.x; acc.y += v.y; acc.z += v.z; acc.w += v.w;
    }
    reinterpret_cast<float4*>(zin)[(size_t)n * C4 + c] = acc;
}

// ---------------- elementwise / graph kernels ----------------
__global__ void vinit_k(float* __restrict__ vf, const float* __restrict__ vemb) {
    int idx = blockIdx.x * blockDim.x + threadIdx.x;
    if (idx >= kG * kH / 4) return;
    reinterpret_cast<float4*>(vf)[idx] =
        reinterpret_cast<const float4*>(vemb)[idx & (kH / 4 - 1)];
}

__global__ void addvirt_k(const float* __restrict__ h, const int* __restrict__ batch,
                          const float* __restrict__ vf, float* __restrict__ out) {
    int idx = blockIdx.x * blockDim.x + threadIdx.x;
    if (idx >= kN * (kH / 4)) return;
    int n = idx >> 7;
    int g = __ldg(batch + n);
    float4 a = reinterpret_cast<const float4*>(h)[idx];
    float4 b = reinterpret_cast<const float4*>(vf)[(g << 7) + (idx & 127)];
    a.x += b.x; a.y += b.y; a.z += b.z; a.w += b.w;
    reinterpret_cast<float4*>(out)[idx] = a;
}

__global__ void pooladd_k(const float* __restrict__ h, const int* __restrict__ batch,
                          float* __restrict__ pool) {
    int idx = blockIdx.x * blockDim.x + threadIdx.x;
    if (idx >= kN * (kH / 4)) return;
    int n = idx >> 7;
    int g = __ldg(batch + n);
    float4 v = reinterpret_cast<const float4*>(h)[idx];
    float* p = pool + (size_t)g * kH + ((idx & 127) << 2);
    atomicAdd(p + 0, v.x);
    atomicAdd(p + 1, v.y);
    atomicAdd(p + 2, v.z);
    atomicAdd(p + 3, v.w);
}

__global__ void count_k(const int* __restrict__ batch, int* __restrict__ cnt) {
    int n = blockIdx.x * blockDim.x + threadIdx.x;
    if (n < kN) atomicAdd(&cnt[__ldg(batch + n)], 1);
}

__global__ void div_k(float* __restrict__ out, const int* __restrict__ cnt) {
    int idx = blockIdx.x * blockDim.x + threadIdx.x;
    if (idx >= kG * kH) return;
    int g = idx >> 9;
    out[idx] /= fmaxf((float)cnt[g], 1.0f);
}

// ---------------- host launcher ----------------
static void run_gemm(const __nv_bfloat16* Ahi, const __nv_bfloat16* Alo,
                     const __nv_bfloat16* Bhi, const __nv_bfloat16* Blo,
                     const float* lb, const float* ga, const float* be,
                     float* C, __nv_bfloat16* Chi, __nv_bfloat16* Clo,
                     int M, int K, int Nc, bool relu, bool split) {
    dim3 grid(Nc / 256, (M + 127) / 128);
    if (split) {
        if (relu) gemm_bf16<1,1><<<grid, 256, DSMEM>>>(Ahi, Alo, Bhi, Blo, lb, ga, be, C, Chi, Clo, M, K, Nc);
        else      gemm_bf16<0,1><<<grid, 256, DSMEM>>>(Ahi, Alo, Bhi, Blo, lb, ga, be, C, Chi, Clo, M, K, Nc);
    } else {
        if (relu) gemm_bf16<1,0><<<grid, 256, DSMEM>>>(Ahi, Alo, Bhi, Blo, lb, ga, be, C, Chi, Clo, M, K, Nc);
        else      gemm_bf16<0,0><<<grid, 256, DSMEM>>>(Ahi, Alo, Bhi, Blo, lb, ga, be, C, Chi, Clo, M, K, Nc);
    }
}

static void run_split(const float* A, __nv_bfloat16* hi, __nv_bfloat16* lo, size_t n) {
    int n4 = (int)(n / 4);
    split_k<<<(n4 + 255) / 256, 256>>>(A, hi, lo, n4);
}

extern "C" void kernel_launch(void* const* d_in, const int* in_sizes, int n_in,
                              void* d_out, int out_size) {
    const float* x      = (const float*)d_in[0];
    const int*   ei     = (const int*)  d_in[1];
    const int*   batch  = (const int*)  d_in[2];
    const float* c1_W1  = (const float*)d_in[3];
    const float* c1_b1  = (const float*)d_in[4];
    const float* c1_g1  = (const float*)d_in[5];
    const float* c1_be1 = (const float*)d_in[6];
    const float* c1_W2  = (const float*)d_in[7];
    const float* c1_b2  = (const float*)d_in[8];
    const float* bn1_g  = (const float*)d_in[9];
    const float* bn1_b  = (const float*)d_in[10];
    const float* cs_W1  = (const float*)d_in[11];
    const float* cs_b1  = (const float*)d_in[12];
    const float* cs_g1  = (const float*)d_in[13];
    const float* cs_be1 = (const float*)d_in[14];
    const float* cs_W2  = (const float*)d_in[15];
    const float* cs_b2  = (const float*)d_in[16];
    const float* bns_g  = (const float*)d_in[17];
    const float* bns_b  = (const float*)d_in[18];
    const float* vemb   = (const float*)d_in[19];
    const float* v_W1   = (const float*)d_in[20];
    const float* v_b1   = (const float*)d_in[21];
    const float* v_g1   = (const float*)d_in[22];
    const float* v_be1  = (const float*)d_in[23];
    const float* v_W2   = (const float*)d_in[24];
    const float* v_b2   = (const float*)d_in[25];
    const float* v_g2   = (const float*)d_in[26];
    const float* v_be2  = (const float*)d_in[27];

    cudaFuncSetAttribute(gemm_bf16<0,0>, cudaFuncAttributeMaxDynamicSharedMemorySize, DSMEM);
    cudaFuncSetAttribute(gemm_bf16<0,1>, cudaFuncAttributeMaxDynamicSharedMemorySize, DSMEM);
    cudaFuncSetAttribute(gemm_bf16<1,0>, cudaFuncAttributeMaxDynamicSharedMemorySize, DSMEM);
    cudaFuncSetAttribute(gemm_bf16<1,1>, cudaFuncAttributeMaxDynamicSharedMemorySize, DSMEM);

    float *hv, *zin, *h, *vf, *pool;
    int *cnt, *deg, *cur, *rowptr, *esrc;
    __nv_bfloat16 *wthi, *wtlo, *ahi, *alo, *bhi, *blo, *phi, *plo, *qhi, *qlo;
    cudaGetSymbolAddress((void**)&hv,     g_hv);
    cudaGetSymbolAddress((void**)&zin,    g_zin);
    cudaGetSymbolAddress((void**)&h,      g_h);
    cudaGetSymbolAddress((void**)&vf,     g_vf);
    cudaGetSymbolAddress((void**)&pool,   g_pool);
    cudaGetSymbolAddress((void**)&cnt,    g_cnt);
    cudaGetSymbolAddress((void**)&deg,    g_deg);
    cudaGetSymbolAddress((void**)&cur,    g_cur);
    cudaGetSymbolAddress((void**)&rowptr, g_rowptr);
    cudaGetSymbolAddress((void**)&esrc,   g_esrc);
    cudaGetSymbolAddress((void**)&wthi,   g_wthi);
    cudaGetSymbolAddress((void**)&wtlo,   g_wtlo);
    cudaGetSymbolAddress((void**)&ahi,    g_ahi);
    cudaGetSymbolAddress((void**)&alo,    g_alo);
    cudaGetSymbolAddress((void**)&bhi,    g_bhi);
    cudaGetSymbolAddress((void**)&blo,    g_blo);
    cudaGetSymbolAddress((void**)&phi,    g_phi);
    cudaGetSymbolAddress((void**)&plo,    g_plo);
    cudaGetSymbolAddress((void**)&qhi,    g_qhi);
    cudaGetSymbolAddress((void**)&qlo,    g_qlo);

    const int* srcI = ei;
    const int* dstI = ei + kE;

    // ---- CSR build ----
    cudaMemsetAsync(deg, 0, kN * sizeof(int));
    cudaMemsetAsync(cur, 0, kN * sizeof(int));
    degcount_k<<<(kE + 255) / 256, 256>>>(dstI, deg);
    scan_k<<<1, 1024>>>(deg, rowptr);
    fill_k<<<(kE + 255) / 256, 256>>>(srcI, dstI, rowptr, cur, esrc);

    // ---- weight splits ----
    run_split(c1_W1, wthi + OFF_c1W1, wtlo + OFF_c1W1, (size_t)kD * kH2);
    run_split(c1_W2, wthi + OFF_c1W2, wtlo + OFF_c1W2, (size_t)kH2 * kH);
    for (int i = 0; i < kL; i++) {
        run_split(cs_W1 + (size_t)i * kH * kH2,
                  wthi + OFF_csW1 + (size_t)i * kH * kH2,
                  wtlo + OFF_csW1 + (size_t)i * kH * kH2, (size_t)kH * kH2);
        run_split(cs_W2 + (size_t)i * kH2 * kH,
                  wthi + OFF_csW2 + (size_t)i * kH2 * kH,
                  wtlo + OFF_csW2 + (size_t)i * kH2 * kH, (size_t)kH2 * kH);
    }
    run_split(v_W1, wthi + OFF_vW1, wtlo + OFF_vW1, (size_t)kH * kH2);
    run_split(v_W2, wthi + OFF_vW2, wtlo + OFF_vW2, (size_t)kH2 * kH);

    // virtual node features
    vinit_k<<<(kG * kH / 4 + 255) / 256, 256>>>(vf, vemb);

    // ---- conv1: zin = x + agg(x); MLP 128 -> 1024 -> 512 ----
    aggregate_k<kD><<<kN, kD / 4>>>(x, rowptr, esrc, zin);
    run_split(zin, ahi, alo, (size_t)kN * kD);
    run_gemm(ahi, alo, wthi + OFF_c1W1, wtlo + OFF_c1W1, c1_b1, c1_g1, c1_be1,
             nullptr, bhi, blo, kN, kD, kH2, true, true);
    run_gemm(bhi, blo, wthi + OFF_c1W2, wtlo + OFF_c1W2, c1_b2, bn1_g, bn1_b,
             h, nullptr, nullptr, kN, kH2, kH, true, false);

    // ---- L GIN layers with virtual node ----
    for (int i = 0; i < kL; i++) {
        addvirt_k<<<(kN * (kH / 4) + 255) / 256, 256>>>(h, batch, vf, hv);
        aggregate_k<kH><<<kN, kH / 4>>>(hv, rowptr, esrc, zin);
        run_split(zin, ahi, alo, (size_t)kN * kH);
        run_gemm(ahi, alo, wthi + OFF_csW1 + (size_t)i * kH * kH2,
                 wtlo + OFF_csW1 + (size_t)i * kH * kH2,
                 cs_b1 + i * kH2, cs_g1 + i * kH2, cs_be1 + i * kH2,
                 nullptr, bhi, blo, kN, kH, kH2, true, true);
        run_gemm(bhi, blo, wthi + OFF_csW2 + (size_t)i * kH2 * kH,
                 wtlo + OFF_csW2 + (size_t)i * kH2 * kH,
                 cs_b2 + i * kH, bns_g + i * kH, bns_b + i * kH,
                 h, nullptr, nullptr, kN, kH2, kH, i < kL - 1, false);
        if (i < kL - 1) {
            cudaMemcpyAsync(pool, vf, (size_t)kG * kH * sizeof(float), cudaMemcpyDeviceToDevice);
            pooladd_k<<<(kN * (kH / 4) + 255) / 256, 256>>>(h, batch, pool);
            run_split(pool, phi, plo, (size_t)kG * kH);
            run_gemm(phi, plo, wthi + OFF_vW1, wtlo + OFF_vW1, v_b1, v_g1, v_be1,
                     nullptr, qhi, qlo, kG, kH, kH2, true, true);
            run_gemm(qhi, qlo, wthi + OFF_vW2, wtlo + OFF_vW2, v_b2, v_g2, v_be2,
                     vf, nullptr, nullptr, kG, kH2, kH, true, false);
        }
    }

    // ---- mean-pool readout into d_out ----
    float* outp = (float*)d_out;
    cudaMemsetAsync(outp, 0, (size_t)kG * kH * sizeof(float));
    cudaMemsetAsync(cnt, 0, kG * sizeof(int));
    count_k<<<(kN + 255) / 256, 256>>>(batch, cnt);
    pooladd_k<<<(kN * (kH / 4) + 255) / 256, 256>>>(h, batch, outp);
    div_k<<<(kG * kH + 255) / 256, 256>>>(outp, cnt);
}

// round 10
// speedup vs baseline: 3.3555x; 1.0146x over previous
#include <cuda_runtime.h>
#include <cuda_bf16.h>
#include <mma.h>
#include <cstdint>

using namespace nvcuda;

// Problem constants
constexpr int kN  = 50000;
constexpr int kE  = 800000;
constexpr int kG  = 128;
constexpr int kD  = 128;
constexpr int kH  = 512;
constexpr int kH2 = 1024;
constexpr int kL  = 4;
#define BNS 0.9999950000374997f   // 1/sqrt(1+1e-5)

// ---------------- scratch (no cudaMalloc allowed) ----------------
__device__ float g_hv  [(size_t)kN * kH];
__device__ float g_h   [(size_t)kN * kH];
__device__ float g_vf  [kG * kH];
__device__ float g_pool[kG * kH];
__device__ int   g_cnt [kG];

// CSR structures
__device__ int g_deg   [kN];
__device__ int g_cur   [kN];
__device__ int g_rowptr[kN + 1];
__device__ int g_esrc  [kE];

// bf16 split buffers
__device__ __nv_bfloat16 g_ahi[(size_t)kN * kH];   // aggregated input split (GEMM1 input)
__device__ __nv_bfloat16 g_alo[(size_t)kN * kH];
__device__ __nv_bfloat16 g_bhi[(size_t)kN * kH2];  // GEMM1 output split
__device__ __nv_bfloat16 g_blo[(size_t)kN * kH2];
__device__ __nv_bfloat16 g_phi[kG * kH];           // pool split
__device__ __nv_bfloat16 g_plo[kG * kH];
__device__ __nv_bfloat16 g_qhi[kG * kH2];          // zv split
__device__ __nv_bfloat16 g_qlo[kG * kH2];

// Split weights, layout [K, Nc] row-major, bf16 hi/lo
constexpr size_t OFF_c1W1 = 0;                            // [128,1024]
constexpr size_t OFF_c1W2 = OFF_c1W1 + 128 * 1024;        // [1024,512]
constexpr size_t OFF_csW1 = OFF_c1W2 + 1024 * 512;        // 4 x [512,1024]
constexpr size_t OFF_csW2 = OFF_csW1 + 4ull * 512 * 1024; // 4 x [1024,512]
constexpr size_t OFF_vW1  = OFF_csW2 + 4ull * 1024 * 512; // [512,1024]
constexpr size_t OFF_vW2  = OFF_vW1 + 512 * 1024;         // [1024,512]
constexpr size_t WT_TOTAL = OFF_vW2 + 1024 * 512;
__device__ __nv_bfloat16 g_wthi[WT_TOTAL];
__device__ __nv_bfloat16 g_wtlo[WT_TOTAL];

// ---------------- helpers ----------------
__device__ __forceinline__ uint32_t smem_u32(const void* p) {
    uint32_t a;
    asm("{ .reg .u64 t; cvta.to.shared.u64 t, %1; cvt.u32.u64 %0, t; }" : "=r"(a) : "l"(p));
    return a;
}
__device__ __forceinline__ void cp16(uint32_t saddr, const void* gaddr) {
    asm volatile("cp.async.cg.shared.global [%0], [%1], 16;" :: "r"(saddr), "l"(gaddr) : "memory");
}
#define CP_COMMIT() asm volatile("cp.async.commit_group;" ::: "memory")
#define CP_WAIT(n)  asm volatile("cp.async.wait_group %0;" :: "n"(n) : "memory")

// pack 4 floats -> hi/lo bf16 pairs (uint2 each)
__device__ __forceinline__ void split4(float4 v, uint2& uh, uint2& ul) {
    unsigned short hx = __bfloat16_as_ushort(__float2bfloat16(v.x));
    unsigned short hy = __bfloat16_as_ushort(__float2bfloat16(v.y));
    unsigned short hz = __bfloat16_as_ushort(__float2bfloat16(v.z));
    unsigned short hw = __bfloat16_as_ushort(__float2bfloat16(v.w));
    float fx = __bfloat162float(__ushort_as_bfloat16(hx));
    float fy = __bfloat162float(__ushort_as_bfloat16(hy));
    float fz = __bfloat162float(__ushort_as_bfloat16(hz));
    float fw = __bfloat162float(__ushort_as_bfloat16(hw));
    unsigned short lx = __bfloat16_as_ushort(__float2bfloat16(v.x - fx));
    unsigned short ly = __bfloat16_as_ushort(__float2bfloat16(v.y - fy));
    unsigned short lz = __bfloat16_as_ushort(__float2bfloat16(v.z - fz));
    unsigned short lw = __bfloat16_as_ushort(__float2bfloat16(v.w - fw));
    uh.x = (uint32_t)hx | ((uint32_t)hy << 16);
    uh.y = (uint32_t)hz | ((uint32_t)hw << 16);
    ul.x = (uint32_t)lx | ((uint32_t)ly << 16);
    ul.y = (uint32_t)lz | ((uint32_t)lw << 16);
}

// ---------------- GEMM smem layout (tile 128x256, BK=32, 4 stages) ----------------
constexpr int A_LD   = 40;                  // 32 + 8 pad
constexpr int B_LD   = 264;                 // 256 + 8 pad
constexpr int A_MATB = 128 * A_LD * 2;      // 10240 bytes per A matrix
constexpr int B_MATB = 32 * B_LD * 2;       // 16896 bytes per B matrix
constexpr int ST_AH  = 0;
constexpr int ST_AL  = A_MATB;
constexpr int ST_BH  = 2 * A_MATB;
constexpr int ST_BL  = 2 * A_MATB + B_MATB;
constexpr int STAGE  = 2 * A_MATB + 2 * B_MATB; // 54272
constexpr int NSTG   = 4;
constexpr int OFF_SC = NSTG * STAGE;        // 217088
constexpr int OFF_SH = OFF_SC + 1024;
constexpr int DSMEM  = OFF_SH + 1024;       // 219136

// ---------------- bf16-split GEMM: out = act((A@W + lb)*(ga*BNS) + be) ----------------
// CTA 128x256, 8 warps (2x4), warp tile 64x64, wmma 16x16x16, 3-term split, 4-stage cp.async.
template<int RELU, int SPLIT>
__global__ void __launch_bounds__(256, 1) gemm_bf16(
    const __nv_bfloat16* __restrict__ Ahi, const __nv_bfloat16* __restrict__ Alo,
    const __nv_bfloat16* __restrict__ Bhi, const __nv_bfloat16* __restrict__ Blo,
    const float* __restrict__ lb, const float* __restrict__ ga,
    const float* __restrict__ be, float* __restrict__ C,
    __nv_bfloat16* __restrict__ Chi, __nv_bfloat16* __restrict__ Clo,
    int M, int K, int Nc)
{
    extern __shared__ char sm[];
    const uint32_t sbase = smem_u32(sm);

    const int tid  = threadIdx.x;
    const int warp = tid >> 5, lane = tid & 31;
    const int wm   = warp >> 2, wn = warp & 3;
    const int bm0  = blockIdx.y * 128, bn0 = blockIdx.x * 256;

    // fused BN params for this 256-column tile
    {
        float s = ga[bn0 + tid] * BNS;
        ((float*)(sm + OFF_SC))[tid] = s;
        ((float*)(sm + OFF_SH))[tid] = fmaf(lb[bn0 + tid], s, be[bn0 + tid]);
    }

    wmma::fragment<wmma::accumulator, 16, 16, 16, float> acc[4][4];
#pragma unroll
    for (int i = 0; i < 4; i++)
#pragma unroll
        for (int j = 0; j < 4; j++) wmma::fill_fragment(acc[i][j], 0.0f);

    const int nK = K >> 5;

    auto issue = [&](int c) {
        const int buf = c & 3;   // NSTG = 4
        const int k0  = c << 5;
        const uint32_t sb = sbase + buf * STAGE;
#pragma unroll
        for (int t = 0; t < 2; t++) {
            int chunk = tid + (t << 8);
            int row   = chunk >> 2;
            int col8  = (chunk & 3) << 3;
            int gr    = bm0 + row;
            if (gr < M) {
                uint32_t off = (uint32_t)(row * A_LD + col8) * 2;
                size_t g = (size_t)gr * K + k0 + col8;
                cp16(sb + ST_AH + off, Ahi + g);
                cp16(sb + ST_AL + off, Alo + g);
            }
        }
#pragma unroll
        for (int t = 0; t < 4; t++) {
            int chunk = tid + (t << 8);
            int row   = chunk >> 5;
            int col8  = (chunk & 31) << 3;
            uint32_t off = (uint32_t)(row * B_LD + col8) * 2;
            size_t g = (size_t)(k0 + row) * Nc + bn0 + col8;
            cp16(sb + ST_BH + off, Bhi + g);
            cp16(sb + ST_BL + off, Blo + g);
        }
        CP_COMMIT();
    };

    issue(0);
    if (nK > 1) issue(1);
    if (nK > 2) issue(2);
    for (int c = 0; c < nK; c++) {
        const int rem = nK - 1 - c;
        if (rem >= 2)      { CP_WAIT(2); }
        else if (rem == 1) { CP_WAIT(1); }
        else               { CP_WAIT(0); }
        __syncthreads();
        if (c + 3 < nK) issue(c + 3);

        const char* st = sm + (c & 3) * STAGE;
        const __nv_bfloat16* sAh = (const __nv_bfloat16*)(st + ST_AH);
        const __nv_bfloat16* sAl = (const __nv_bfloat16*)(st + ST_AL);
        const __nv_bfloat16* sBh = (const __nv_bfloat16*)(st + ST_BH);
        const __nv_bfloat16* sBl = (const __nv_bfloat16*)(st + ST_BL);
#pragma unroll
        for (int ks = 0; ks < 2; ks++) {
            const int kk = ks << 4;
            wmma::fragment<wmma::matrix_a, 16, 16, 16, __nv_bfloat16, wmma::row_major> ah[4], al[4];
#pragma unroll
            for (int i = 0; i < 4; i++) {
                wmma::load_matrix_sync(ah[i], sAh + (wm * 64 + i * 16) * A_LD + kk, A_LD);
                wmma::load_matrix_sync(al[i], sAl + (wm * 64 + i * 16) * A_LD + kk, A_LD);
            }
#pragma unroll
            for (int j = 0; j < 4; j++) {
                wmma::fragment<wmma::matrix_b, 16, 16, 16, __nv_bfloat16, wmma::row_major> bh, bl;
                wmma::load_matrix_sync(bh, sBh + kk * B_LD + wn * 64 + j * 16, B_LD);
                wmma::load_matrix_sync(bl, sBl + kk * B_LD + wn * 64 + j * 16, B_LD);
#pragma unroll
                for (int i = 0; i < 4; i++) {
                    wmma::mma_sync(acc[i][j], ah[i], bh, acc[i][j]);
                    wmma::mma_sync(acc[i][j], ah[i], bl, acc[i][j]);
                    wmma::mma_sync(acc[i][j], al[i], bh, acc[i][j]);
                }
            }
        }
        __syncthreads();
    }

    // epilogue: stage 16x16 tiles via smem, fused BN/bias/ReLU (+optional split)
    float* stage = (float*)(sm + warp * 1280);   // 16 rows * ld 20
    const float* sc = (const float*)(sm + OFF_SC);
    const float* sh = (const float*)(sm + OFF_SH);
#pragma unroll
    for (int i = 0; i < 4; i++)
#pragma unroll
        for (int j = 0; j < 4; j++) {
            __syncwarp();
            wmma::store_matrix_sync(stage, acc[i][j], 20, wmma::mem_row_major);
            __syncwarp();
#pragma unroll
            for (int t = lane; t < 256; t += 32) {
                int r   = t >> 4, cc = t & 15;
                int gr  = bm0 + wm * 64 + i * 16 + r;
                int gcl = wn * 64 + j * 16 + cc;
                if (gr < M) {
                    float o = fmaf(stage[r * 20 + cc], sc[gcl], sh[gcl]);
                    if (RELU) o = fmaxf(o, 0.0f);
                    size_t idx = (size_t)gr * Nc + bn0 + gcl;
                    if (SPLIT) {
                        __nv_bfloat16 hi = __float2bfloat16(o);
                        Chi[idx] = hi;
                        Clo[idx] = __float2bfloat16(o - __bfloat162float(hi));
                    } else {
                        C[idx] = o;
                    }
                }
            }
        }
}

// ---------------- fp32 -> bf16 hi/lo split (weights / small buffers) ----------------
__global__ void split_k(const float* __restrict__ A, __nv_bfloat16* __restrict__ hi,
                        __nv_bfloat16* __restrict__ lo, int n4) {
    int i = blockIdx.x * blockDim.x + threadIdx.x;
    if (i >= n4) return;
    float4 v = reinterpret_cast<const float4*>(A)[i];
    uint2 uh, ul;
    split4(v, uh, ul);
    reinterpret_cast<uint2*>(hi)[i] = uh;
    reinterpret_cast<uint2*>(lo)[i] = ul;
}

// ---------------- CSR build ----------------
__global__ void degcount_k(const int* __restrict__ dst, int* __restrict__ deg) {
    int e = blockIdx.x * blockDim.x + threadIdx.x;
    if (e < kE) atomicAdd(&deg[__ldg(dst + e)], 1);
}

__global__ void scan_k(const int* __restrict__ deg, int* __restrict__ rowptr) {
    __shared__ int part[1024];
    __shared__ int total;
    const int t  = threadIdx.x;
    const int CH = (kN + 1023) / 1024;
    int start = t * CH;
    int end   = start + CH; if (end > kN) end = kN;
    int s = 0;
    for (int i = start; i < end; i++) s += deg[i];
    part[t] = s;
    __syncthreads();
    if (t == 0) {
        int run = 0;
        for (int j = 0; j < 1024; j++) { int v = part[j]; part[j] = run; run += v; }
        total = run;
    }
    __syncthreads();
    int run = part[t];
    for (int i = start; i < end; i++) { rowptr[i] = run; run += deg[i]; }
    if (t == 0) rowptr[kN] = total;
}

__global__ void fill_k(const int* __restrict__ src, const int* __restrict__ dst,
                       const int* __restrict__ rowptr, int* __restrict__ cur,
                       int* __restrict__ esrc) {
    int e = blockIdx.x * blockDim.x + threadIdx.x;
    if (e >= kE) return;
    int d = __ldg(dst + e);
    int pos = rowptr[d] + atomicAdd(&cur[d], 1);
    esrc[pos] = __ldg(src + e);
}

// ---------------- CSR gather aggregation + fused hi/lo split ----------------
// out[n] = feat[n] + sum_{s in N(n)} feat[s], written as bf16 hi/lo.
template<int F>
__global__ void __launch_bounds__(256) aggregate_k(
    const float* __restrict__ feat,
    const int* __restrict__ rowptr, const int* __restrict__ esrc,
    __nv_bfloat16* __restrict__ hi, __nv_bfloat16* __restrict__ lo)
{
    constexpr int C4  = F / 4;
    constexpr int NPB = 256 / C4;
    const int n = blockIdx.x * NPB + (threadIdx.x / C4);
    const int c = threadIdx.x & (C4 - 1);
    const float4* f4 = reinterpret_cast<const float4*>(feat);
    float4 acc = f4[(size_t)n * C4 + c];
    const int p0 = __ldg(rowptr + n), p1 = __ldg(rowptr + n + 1);
    int p = p0;
    for (; p + 4 <= p1; p += 4) {
        int s0 = __ldg(esrc + p),     s1 = __ldg(esrc + p + 1);
        int s2 = __ldg(esrc + p + 2), s3 = __ldg(esrc + p + 3);
        float4 v0 = f4[(size_t)s0 * C4 + c];
        float4 v1 = f4[(size_t)s1 * C4 + c];
        float4 v2 = f4[(size_t)s2 * C4 + c];
        float4 v3 = f4[(size_t)s3 * C4 + c];
        acc.x += (v0.x + v1.x) + (v2.x + v3.x);
        acc.y += (v0.y + v1.y) + (v2.y + v3.y);
        acc.z += (v0.z + v1.z) + (v2.z + v3.z);
        acc.w += (v0.w + v1.w) + (v2.w + v3.w);
    }
    for (; p < p1; p++) {
        int s = __ldg(esrc + p);
        float4 v = f4[(size_t)s * C4 + c];
        acc.x += v.x; acc.y += v.y; acc.z += v.z; acc.w += v.w;
    }
    uint2 uh, ul;
    split4(acc, uh, ul);
    reinterpret_cast<uint2*>(hi)[(size_t)n * C4 + c] = uh;
    reinterpret_cast<uint2*>(lo)[(size_t)n * C4 + c] = ul;
}

// ---------------- elementwise / graph kernels ----------------
__global__ void vinit_k(float* __restrict__ vf, const float* __restrict__ vemb) {
    int idx = blockIdx.x * blockDim.x + threadIdx.x;
    if (idx >= kG * kH / 4) return;
    reinterpret_cast<float4*>(vf)[idx] =
        reinterpret_cast<const float4*>(vemb)[idx & (kH / 4 - 1)];
}

__global__ void addvirt_k(const float* __restrict__ h, const int* __restrict__ batch,
                          const float* __restrict__ vf, float* __restrict__ out) {
    int idx = blockIdx.x * blockDim.x + threadIdx.x;
    if (idx >= kN * (kH / 4)) return;
    int n = idx >> 7;
    int g = __ldg(batch + n);
    float4 a = reinterpret_cast<const float4*>(h)[idx];
    float4 b = reinterpret_cast<const float4*>(vf)[(g << 7) + (idx & 127)];
    a.x += b.x; a.y += b.y; a.z += b.z; a.w += b.w;
    reinterpret_cast<float4*>(out)[idx] = a;
}

__global__ void pooladd_k(const float* __restrict__ h, const int* __restrict__ batch,
                          float* __restrict__ pool) {
    int idx = blockIdx.x * blockDim.x + threadIdx.x;
    if (idx >= kN * (kH / 4)) return;
    int n = idx >> 7;
    int g = __ldg(batch + n);
    float4 v = reinterpret_cast<const float4*>(h)[idx];
    float* p = pool + (size_t)g * kH + ((idx & 127) << 2);
    atomicAdd(p + 0, v.x);
    atomicAdd(p + 1, v.y);
    atomicAdd(p + 2, v.z);
    atomicAdd(p + 3, v.w);
}

__global__ void count_k(const int* __restrict__ batch, int* __restrict__ cnt) {
    int n = blockIdx.x * blockDim.x + threadIdx.x;
    if (n < kN) atomicAdd(&cnt[__ldg(batch + n)], 1);
}

__global__ void div_k(float* __restrict__ out, const int* __restrict__ cnt) {
    int idx = blockIdx.x * blockDim.x + threadIdx.x;
    if (idx >= kG * kH) return;
    int g = idx >> 9;
    out[idx] /= fmaxf((float)cnt[g], 1.0f);
}

// ---------------- host launcher ----------------
static void run_gemm(const __nv_bfloat16* Ahi, const __nv_bfloat16* Alo,
                     const __nv_bfloat16* Bhi, const __nv_bfloat16* Blo,
                     const float* lb, const float* ga, const float* be,
                     float* C, __nv_bfloat16* Chi, __nv_bfloat16* Clo,
                     int M, int K, int Nc, bool relu, bool split) {
    dim3 grid(Nc / 256, (M + 127) / 128);
    if (split) {
        if (relu) gemm_bf16<1,1><<<grid, 256, DSMEM>>>(Ahi, Alo, Bhi, Blo, lb, ga, be, C, Chi, Clo, M, K, Nc);
        else      gemm_bf16<0,1><<<grid, 256, DSMEM>>>(Ahi, Alo, Bhi, Blo, lb, ga, be, C, Chi, Clo, M, K, Nc);
    } else {
        if (relu) gemm_bf16<1,0><<<grid, 256, DSMEM>>>(Ahi, Alo, Bhi, Blo, lb, ga, be, C, Chi, Clo, M, K, Nc);
        else      gemm_bf16<0,0><<<grid, 256, DSMEM>>>(Ahi, Alo, Bhi, Blo, lb, ga, be, C, Chi, Clo, M, K, Nc);
    }
}

static void run_split(const float* A, __nv_bfloat16* hi, __nv_bfloat16* lo, size_t n) {
    int n4 = (int)(n / 4);
    split_k<<<(n4 + 255) / 256, 256>>>(A, hi, lo, n4);
}

extern "C" void kernel_launch(void* const* d_in, const int* in_sizes, int n_in,
                              void* d_out, int out_size) {
    const float* x      = (const float*)d_in[0];
    const int*   ei     = (const int*)  d_in[1];
    const int*   batch  = (const int*)  d_in[2];
    const float* c1_W1  = (const float*)d_in[3];
    const float* c1_b1  = (const float*)d_in[4];
    const float* c1_g1  = (const float*)d_in[5];
    const float* c1_be1 = (const float*)d_in[6];
    const float* c1_W2  = (const float*)d_in[7];
    const float* c1_b2  = (const float*)d_in[8];
    const float* bn1_g  = (const float*)d_in[9];
    const float* bn1_b  = (const float*)d_in[10];
    const float* cs_W1  = (const float*)d_in[11];
    const float* cs_b1  = (const float*)d_in[12];
    const float* cs_g1  = (const float*)d_in[13];
    const float* cs_be1 = (const float*)d_in[14];
    const float* cs_W2  = (const float*)d_in[15];
    const float* cs_b2  = (const float*)d_in[16];
    const float* bns_g  = (const float*)d_in[17];
    const float* bns_b  = (const float*)d_in[18];
    const float* vemb   = (const float*)d_in[19];
    const float* v_W1   = (const float*)d_in[20];
    const float* v_b1   = (const float*)d_in[21];
    const float* v_g1   = (const float*)d_in[22];
    const float* v_be1  = (const float*)d_in[23];
    const float* v_W2   = (const float*)d_in[24];
    const float* v_b2   = (const float*)d_in[25];
    const float* v_g2   = (const float*)d_in[26];
    const float* v_be2  = (const float*)d_in[27];

    cudaFuncSetAttribute(gemm_bf16<0,0>, cudaFuncAttributeMaxDynamicSharedMemorySize, DSMEM);
    cudaFuncSetAttribute(gemm_bf16<0,1>, cudaFuncAttributeMaxDynamicSharedMemorySize, DSMEM);
    cudaFuncSetAttribute(gemm_bf16<1,0>, cudaFuncAttributeMaxDynamicSharedMemorySize, DSMEM);
    cudaFuncSetAttribute(gemm_bf16<1,1>, cudaFuncAttributeMaxDynamicSharedMemorySize, DSMEM);

    float *hv, *h, *vf, *pool;
    int *cnt, *deg, *cur, *rowptr, *esrc;
    __nv_bfloat16 *wthi, *wtlo, *ahi, *alo, *bhi, *blo, *phi, *plo, *qhi, *qlo;
    cudaGetSymbolAddress((void**)&hv,     g_hv);
    cudaGetSymbolAddress((void**)&h,      g_h);
    cudaGetSymbolAddress((void**)&vf,     g_vf);
    cudaGetSymbolAddress((void**)&pool,   g_pool);
    cudaGetSymbolAddress((void**)&cnt,    g_cnt);
    cudaGetSymbolAddress((void**)&deg,    g_deg);
    cudaGetSymbolAddress((void**)&cur,    g_cur);
    cudaGetSymbolAddress((void**)&rowptr, g_rowptr);
    cudaGetSymbolAddress((void**)&esrc,   g_esrc);
    cudaGetSymbolAddress((void**)&wthi,   g_wthi);
    cudaGetSymbolAddress((void**)&wtlo,   g_wtlo);
    cudaGetSymbolAddress((void**)&ahi,    g_ahi);
    cudaGetSymbolAddress((void**)&alo,    g_alo);
    cudaGetSymbolAddress((void**)&bhi,    g_bhi);
    cudaGetSymbolAddress((void**)&blo,    g_blo);
    cudaGetSymbolAddress((void**)&phi,    g_phi);
    cudaGetSymbolAddress((void**)&plo,    g_plo);
    cudaGetSymbolAddress((void**)&qhi,    g_qhi);
    cudaGetSymbolAddress((void**)&qlo,    g_qlo);

    const int* srcI = ei;
    const int* dstI = ei + kE;

    // ---- CSR build ----
    cudaMemsetAsync(deg, 0, kN * sizeof(int));
    cudaMemsetAsync(cur, 0, kN * sizeof(int));
    degcount_k<<<(kE + 255) / 256, 256>>>(dstI, deg);
    scan_k<<<1, 1024>>>(deg, rowptr);
    fill_k<<<(kE + 255) / 256, 256>>>(srcI, dstI, rowptr, cur, esrc);

    // ---- weight splits ----
    run_split(c1_W1, wthi + OFF_c1W1, wtlo + OFF_c1W1, (size_t)kD * kH2);
    run_split(c1_W2, wthi + OFF_c1W2, wtlo + OFF_c1W2, (size_t)kH2 * kH);
    for (int i = 0; i < kL; i++) {
        run_split(cs_W1 + (size_t)i * kH * kH2,
                  wthi + OFF_csW1 + (size_t)i * kH * kH2,
                  wtlo + OFF_csW1 + (size_t)i * kH * kH2, (size_t)kH * kH2);
        run_split(cs_W2 + (size_t)i * kH2 * kH,
                  wthi + OFF_csW2 + (size_t)i * kH2 * kH,
                  wtlo + OFF_csW2 + (size_t)i * kH2 * kH, (size_t)kH2 * kH);
    }
    run_split(v_W1, wthi + OFF_vW1, wtlo + OFF_vW1, (size_t)kH * kH2);
    run_split(v_W2, wthi + OFF_vW2, wtlo + OFF_vW2, (size_t)kH2 * kH);

    // virtual node features
    vinit_k<<<(kG * kH / 4 + 255) / 256, 256>>>(vf, vemb);

    // ---- conv1: agg(x) -> split; MLP 128 -> 1024 -> 512 ----
    aggregate_k<kD><<<kN / (256 / (kD / 4)), 256>>>(x, rowptr, esrc, ahi, alo);
    run_gemm(ahi, alo, wthi + OFF_c1W1, wtlo + OFF_c1W1, c1_b1, c1_g1, c1_be1,
             nullptr, bhi, blo, kN, kD, kH2, true, true);
    run_gemm(bhi, blo, wthi + OFF_c1W2, wtlo + OFF_c1W2, c1_b2, bn1_g, bn1_b,
             h, nullptr, nullptr, kN, kH2, kH, true, false);

    // ---- L GIN layers with virtual node ----
    for (int i = 0; i < kL; i++) {
        addvirt_k<<<(kN * (kH / 4) + 255) / 256, 256>>>(h, batch, vf, hv);
        aggregate_k<kH><<<kN / (256 / (kH / 4)), 256>>>(hv, rowptr, esrc, ahi, alo);
        run_gemm(ahi, alo, wthi + OFF_csW1 + (size_t)i * kH * kH2,
                 wtlo + OFF_csW1 + (size_t)i * kH * kH2,
                 cs_b1 + i * kH2, cs_g1 + i * kH2, cs_be1 + i * kH2,
                 nullptr, bhi, blo, kN, kH, kH2, true, true);
        run_gemm(bhi, blo, wthi + OFF_csW2 + (size_t)i * kH2 * kH,
                 wtlo + OFF_csW2 + (size_t)i * kH2 * kH,
                 cs_b2 + i * kH, bns_g + i * kH, bns_b + i * kH,
                 h, nullptr, nullptr, kN, kH2, kH, i < kL - 1, false);
        if (i < kL - 1) {
            cudaMemcpyAsync(pool, vf, (size_t)kG * kH * sizeof(float), cudaMemcpyDeviceToDevice);
            pooladd_k<<<(kN * (kH / 4) + 255) / 256, 256>>>(h, batch, pool);
            run_split(pool, phi, plo, (size_t)kG * kH);
            run_gemm(phi, plo, wthi + OFF_vW1, wtlo + OFF_vW1, v_b1, v_g1, v_be1,
                     nullptr, qhi, qlo, kG, kH, kH2, true, true);
            run_gemm(qhi, qlo, wthi + OFF_vW2, wtlo + OFF_vW2, v_b2, v_g2, v_be2,
                     vf, nullptr, nullptr, kG, kH2, kH, true, false);
        }
    }

    // ---- mean-pool readout into d_out ----
    float* outp = (float*)d_out;
    cudaMemsetAsync(outp, 0, (size_t)kG * kH * sizeof(float));
    cudaMemsetAsync(cnt, 0, kG * sizeof(int));
    count_k<<<(kN + 255) / 256, 256>>>(batch, cnt);
    pooladd_k<<<(kN * (kH / 4) + 255) / 256, 256>>>(h, batch, outp);
    div_k<<<(kG * kH + 255) / 256, 256>>>(outp, cnt);
}

// round 12
// speedup vs baseline: 3.8706x; 1.1535x over previous
#include <cuda_runtime.h>
#include <cuda_bf16.h>
#include <mma.h>
#include <cstdint>

using namespace nvcuda;

// Problem constants
constexpr int kN  = 50000;
constexpr int kE  = 800000;
constexpr int kG  = 128;
constexpr int kD  = 128;
constexpr int kH  = 512;
constexpr int kH2 = 1024;
constexpr int kL  = 4;
#define BNS 0.9999950000374997f   // 1/sqrt(1+1e-5)

// ---------------- scratch (no cudaMalloc allowed) ----------------
__device__ float g_h   [(size_t)kN * kH];
__device__ float g_vf  [kG * kH];
__device__ int   g_cnt [kG];
__device__ int   g_goff[kG + 1];

// CSR structures
__device__ int g_deg   [kN];
__device__ int g_cur   [kN];
__device__ int g_rowptr[kN + 1];
__device__ int g_esrc  [kE];

// bf16 split buffers
__device__ __nv_bfloat16 g_ahi[(size_t)kN * kH];   // aggregated input split
__device__ __nv_bfloat16 g_alo[(size_t)kN * kH];
__device__ __nv_bfloat16 g_bhi[(size_t)kN * kH2];  // GEMM1 output split
__device__ __nv_bfloat16 g_blo[(size_t)kN * kH2];
__device__ __nv_bfloat16 g_phi[kG * kH];           // pool split
__device__ __nv_bfloat16 g_plo[kG * kH];
__device__ __nv_bfloat16 g_qhi[kG * kH2];          // zv split
__device__ __nv_bfloat16 g_qlo[kG * kH2];

// Split weights, layout [K, Nc] row-major, bf16 hi/lo
constexpr size_t OFF_c1W1 = 0;                            // [128,1024]
constexpr size_t OFF_c1W2 = OFF_c1W1 + 128 * 1024;        // [1024,512]
constexpr size_t OFF_csW1 = OFF_c1W2 + 1024 * 512;        // 4 x [512,1024]
constexpr size_t OFF_csW2 = OFF_csW1 + 4ull * 512 * 1024; // 4 x [1024,512]
constexpr size_t OFF_vW1  = OFF_csW2 + 4ull * 1024 * 512; // [512,1024]
constexpr size_t OFF_vW2  = OFF_vW1 + 512 * 1024;         // [1024,512]
constexpr size_t WT_TOTAL = OFF_vW2 + 1024 * 512;
__device__ __nv_bfloat16 g_wthi[WT_TOTAL];
__device__ __nv_bfloat16 g_wtlo[WT_TOTAL];

// ---------------- helpers ----------------
__device__ __forceinline__ uint32_t smem_u32(const void* p) {
    uint32_t a;
    asm("{ .reg .u64 t; cvta.to.shared.u64 t, %1; cvt.u32.u64 %0, t; }" : "=r"(a) : "l"(p));
    return a;
}
__device__ __forceinline__ void cp16(uint32_t saddr, const void* gaddr) {
    asm volatile("cp.async.cg.shared.global [%0], [%1], 16;" :: "r"(saddr), "l"(gaddr) : "memory");
}
#define CP_COMMIT() asm volatile("cp.async.commit_group;" ::: "memory")
#define CP_WAIT(n)  asm volatile("cp.async.wait_group %0;" :: "n"(n) : "memory")

// pack 4 floats -> hi/lo bf16 pairs
__device__ __forceinline__ void split4(float4 v, uint2& uh, uint2& ul) {
    unsigned short hx = __bfloat16_as_ushort(__float2bfloat16(v.x));
    unsigned short hy = __bfloat16_as_ushort(__float2bfloat16(v.y));
    unsigned short hz = __bfloat16_as_ushort(__float2bfloat16(v.z));
    unsigned short hw = __bfloat16_as_ushort(__float2bfloat16(v.w));
    float fx = __bfloat162float(__ushort_as_bfloat16(hx));
    float fy = __bfloat162float(__ushort_as_bfloat16(hy));
    float fz = __bfloat162float(__ushort_as_bfloat16(hz));
    float fw = __bfloat162float(__ushort_as_bfloat16(hw));
    unsigned short lx = __bfloat16_as_ushort(__float2bfloat16(v.x - fx));
    unsigned short ly = __bfloat16_as_ushort(__float2bfloat16(v.y - fy));
    unsigned short lz = __bfloat16_as_ushort(__float2bfloat16(v.z - fz));
    unsigned short lw = __bfloat16_as_ushort(__float2bfloat16(v.w - fw));
    uh.x = (uint32_t)hx | ((uint32_t)hy << 16);
    uh.y = (uint32_t)hz | ((uint32_t)hw << 16);
    ul.x = (uint32_t)lx | ((uint32_t)ly << 16);
    ul.y = (uint32_t)lz | ((uint32_t)lw << 16);
}

// ---------------- GEMM smem layout (tile 128x128, BK=32, 2 stages) ----------------
constexpr int A_LD   = 40;                  // 32 + 8 pad
constexpr int B_LD   = 136;                 // 128 + 8 pad
constexpr int A_MATB = 128 * A_LD * 2;      // 10240
constexpr int B_MATB = 32 * B_LD * 2;       // 8704
constexpr int ST_AH  = 0;
constexpr int ST_AL  = A_MATB;
constexpr int ST_BH  = 2 * A_MATB;
constexpr int ST_BL  = 2 * A_MATB + B_MATB;
constexpr int STAGE  = 2 * A_MATB + 2 * B_MATB; // 37888
constexpr int NSTG   = 2;
constexpr int OFF_SC = NSTG * STAGE;        // 75776
constexpr int OFF_SH = OFF_SC + 512;
constexpr int DSMEM  = OFF_SH + 512;        // 76800  (x2 CTAs = 150KB <= 228KB)

// ---------------- bf16-split GEMM: out = act((A@W + lb)*(ga*BNS) + be) ----------------
// CTA 128x128, 8 warps (4x2), warp tile 32x64, wmma 16x16x16, 3-term split,
// 2-stage cp.async, 2 CTAs/SM for tensor-pipe overlap.
template<int RELU, int SPLIT>
__global__ void __launch_bounds__(256, 2) gemm_bf16(
    const __nv_bfloat16* __restrict__ Ahi, const __nv_bfloat16* __restrict__ Alo,
    const __nv_bfloat16* __restrict__ Bhi, const __nv_bfloat16* __restrict__ Blo,
    const float* __restrict__ lb, const float* __restrict__ ga,
    const float* __restrict__ be, float* __restrict__ C,
    __nv_bfloat16* __restrict__ Chi, __nv_bfloat16* __restrict__ Clo,
    int M, int K, int Nc)
{
    extern __shared__ char sm[];
    const uint32_t sbase = smem_u32(sm);

    const int tid  = threadIdx.x;
    const int warp = tid >> 5, lane = tid & 31;
    const int wm   = warp >> 1, wn = warp & 1;   // wm 0..3 (32-row), wn 0..1 (64-col)
    const int bm0  = blockIdx.y * 128, bn0 = blockIdx.x * 128;

    // fused BN params for this 128-column tile
    if (tid < 128) {
        float s = ga[bn0 + tid] * BNS;
        ((float*)(sm + OFF_SC))[tid] = s;
        ((float*)(sm + OFF_SH))[tid] = fmaf(lb[bn0 + tid], s, be[bn0 + tid]);
    }

    wmma::fragment<wmma::accumulator, 16, 16, 16, float> acc[2][4];
#pragma unroll
    for (int i = 0; i < 2; i++)
#pragma unroll
        for (int j = 0; j < 4; j++) wmma::fill_fragment(acc[i][j], 0.0f);

    const int nK = K >> 5;

    auto issue = [&](int c) {
        const int buf = c & 1;
        const int k0  = c << 5;
        const uint32_t sb = sbase + buf * STAGE;
        // A: 512 chunks of 16B per matrix (128 rows x 32 cols)
#pragma unroll
        for (int t = 0; t < 2; t++) {
            int chunk = tid + (t << 8);
            int row   = chunk >> 2;
            int col8  = (chunk & 3) << 3;
            int gr    = bm0 + row;
            if (gr < M) {
                uint32_t off = (uint32_t)(row * A_LD + col8) * 2;
                size_t g = (size_t)gr * K + k0 + col8;
                cp16(sb + ST_AH + off, Ahi + g);
                cp16(sb + ST_AL + off, Alo + g);
            }
        }
        // B: 512 chunks per matrix (32 rows x 128 cols)
#pragma unroll
        for (int t = 0; t < 2; t++) {
            int chunk = tid + (t << 8);
            int row   = chunk >> 4;
            int col8  = (chunk & 15) << 3;
            uint32_t off = (uint32_t)(row * B_LD + col8) * 2;
            size_t g = (size_t)(k0 + row) * Nc + bn0 + col8;
            cp16(sb + ST_BH + off, Bhi + g);
            cp16(sb + ST_BL + off, Blo + g);
        }
        CP_COMMIT();
    };

    issue(0);
    for (int c = 0; c < nK; c++) {
        if (c + 1 < nK) { issue(c + 1); CP_WAIT(1); }
        else            { CP_WAIT(0); }
        __syncthreads();

        const char* st = sm + (c & 1) * STAGE;
        const __nv_bfloat16* sAh = (const __nv_bfloat16*)(st + ST_AH);
        const __nv_bfloat16* sAl = (const __nv_bfloat16*)(st + ST_AL);
        const __nv_bfloat16* sBh = (const __nv_bfloat16*)(st + ST_BH);
        const __nv_bfloat16* sBl = (const __nv_bfloat16*)(st + ST_BL);
#pragma unroll
        for (int ks = 0; ks < 2; ks++) {
            const int kk = ks << 4;
            wmma::fragment<wmma::matrix_a, 16, 16, 16, __nv_bfloat16, wmma::row_major> ah[2], al[2];
#pragma unroll
            for (int i = 0; i < 2; i++) {
                wmma::load_matrix_sync(ah[i], sAh + (wm * 32 + i * 16) * A_LD + kk, A_LD);
                wmma::load_matrix_sync(al[i], sAl + (wm * 32 + i * 16) * A_LD + kk, A_LD);
            }
#pragma unroll
            for (int j = 0; j < 4; j++) {
                wmma::fragment<wmma::matrix_b, 16, 16, 16, __nv_bfloat16, wmma::row_major> bh, bl;
                wmma::load_matrix_sync(bh, sBh + kk * B_LD + wn * 64 + j * 16, B_LD);
                wmma::load_matrix_sync(bl, sBl + kk * B_LD + wn * 64 + j * 16, B_LD);
#pragma unroll
                for (int i = 0; i < 2; i++) {
                    wmma::mma_sync(acc[i][j], ah[i], bh, acc[i][j]);
                    wmma::mma_sync(acc[i][j], ah[i], bl, acc[i][j]);
                    wmma::mma_sync(acc[i][j], al[i], bh, acc[i][j]);
                }
            }
        }
        __syncthreads();
    }

    // epilogue: stage 16x16 tiles via smem, fused BN/bias/ReLU (+optional split)
    float* stage = (float*)(sm + warp * 1280);   // 16 rows * ld 20
    const float* sc = (const float*)(sm + OFF_SC);
    const float* sh = (const float*)(sm + OFF_SH);
#pragma unroll
    for (int i = 0; i < 2; i++)
#pragma unroll
        for (int j = 0; j < 4; j++) {
            __syncwarp();
            wmma::store_matrix_sync(stage, acc[i][j], 20, wmma::mem_row_major);
            __syncwarp();
#pragma unroll
            for (int t = lane; t < 256; t += 32) {
                int r   = t >> 4, cc = t & 15;
                int gr  = bm0 + wm * 32 + i * 16 + r;
                int gcl = wn * 64 + j * 16 + cc;
                if (gr < M) {
                    float o = fmaf(stage[r * 20 + cc], sc[gcl], sh[gcl]);
                    if (RELU) o = fmaxf(o, 0.0f);
                    size_t idx = (size_t)gr * Nc + bn0 + gcl;
                    if (SPLIT) {
                        __nv_bfloat16 hi = __float2bfloat16(o);
                        Chi[idx] = hi;
                        Clo[idx] = __float2bfloat16(o - __bfloat162float(hi));
                    } else {
                        C[idx] = o;
                    }
                }
            }
        }
}

// ---------------- fp32 -> bf16 hi/lo split (weights) ----------------
__global__ void split_k(const float* __restrict__ A, __nv_bfloat16* __restrict__ hi,
                        __nv_bfloat16* __restrict__ lo, int n4) {
    int i = blockIdx.x * blockDim.x + threadIdx.x;
    if (i >= n4) return;
    float4 v = reinterpret_cast<const float4*>(A)[i];
    uint2 uh, ul;
    split4(v, uh, ul);
    reinterpret_cast<uint2*>(hi)[i] = uh;
    reinterpret_cast<uint2*>(lo)[i] = ul;
}

// ---------------- CSR build ----------------
__global__ void degcount_k(const int* __restrict__ dst, int* __restrict__ deg) {
    int e = blockIdx.x * blockDim.x + threadIdx.x;
    if (e < kE) atomicAdd(&deg[__ldg(dst + e)], 1);
}

__global__ void scan_k(const int* __restrict__ deg, int* __restrict__ rowptr) {
    __shared__ int part[1024];
    __shared__ int total;
    const int t  = threadIdx.x;
    const int CH = (kN + 1023) / 1024;
    int start = t * CH;
    int end   = start + CH; if (end > kN) end = kN;
    int s = 0;
    for (int i = start; i < end; i++) s += deg[i];
    part[t] = s;
    __syncthreads();
    if (t == 0) {
        int run = 0;
        for (int j = 0; j < 1024; j++) { int v = part[j]; part[j] = run; run += v; }
        total = run;
    }
    __syncthreads();
    int run = part[t];
    for (int i = start; i < end; i++) { rowptr[i] = run; run += deg[i]; }
    if (t == 0) rowptr[kN] = total;
}

__global__ void fill_k(const int* __restrict__ src, const int* __restrict__ dst,
                       const int* __restrict__ rowptr, int* __restrict__ cur,
                       int* __restrict__ esrc) {
    int e = blockIdx.x * blockDim.x + threadIdx.x;
    if (e >= kE) return;
    int d = __ldg(dst + e);
    int pos = rowptr[d] + atomicAdd(&cur[d], 1);
    esrc[pos] = __ldg(src + e);
}

// ---------------- graph-range build (batch is sorted) ----------------
__global__ void count_k(const int* __restrict__ batch, int* __restrict__ cnt) {
    int n = blockIdx.x * blockDim.x + threadIdx.x;
    if (n < kN) atomicAdd(&cnt[__ldg(batch + n)], 1);
}
__global__ void gscan_k(const int* __restrict__ cnt, int* __restrict__ goff) {
    if (threadIdx.x == 0) {
        int run = 0;
        for (int g = 0; g < kG; g++) { goff[g] = run; run += cnt[g]; }
        goff[kG] = run;
    }
}

// ---------------- CSR gather aggregation (+virtual add) + fused hi/lo split ----------------
// out[n] = f(n) + sum_{s in N(n)} f(s), f(n) = feat[n] (+ vf[batch[n]] if VIRT)
template<int F, int VIRT>
__global__ void __launch_bounds__(256) aggregate_k(
    const float* __restrict__ feat, const float* __restrict__ vf,
    const int* __restrict__ batch,
    const int* __restrict__ rowptr, const int* __restrict__ esrc,
    __nv_bfloat16* __restrict__ hi, __nv_bfloat16* __restrict__ lo)
{
    constexpr int C4  = F / 4;
    constexpr int NPB = 256 / C4;
    const int n = blockIdx.x * NPB + (threadIdx.x / C4);
    const int c = threadIdx.x & (C4 - 1);
    const float4* f4  = reinterpret_cast<const float4*>(feat);
    const float4* vf4 = reinterpret_cast<const float4*>(vf);
    float4 acc = f4[(size_t)n * C4 + c];
    if (VIRT) {
        float4 v = vf4[(size_t)__ldg(batch + n) * C4 + c];
        acc.x += v.x; acc.y += v.y; acc.z += v.z; acc.w += v.w;
    }
    const int p0 = __ldg(rowptr + n), p1 = __ldg(rowptr + n + 1);
    int p = p0;
    for (; p + 4 <= p1; p += 4) {
        int s0 = __ldg(esrc + p),     s1 = __ldg(esrc + p + 1);
        int s2 = __ldg(esrc + p + 2), s3 = __ldg(esrc + p + 3);
        float4 v0 = f4[(size_t)s0 * C4 + c];
        float4 v1 = f4[(size_t)s1 * C4 + c];
        float4 v2 = f4[(size_t)s2 * C4 + c];
        float4 v3 = f4[(size_t)s3 * C4 + c];
        if (VIRT) {
            float4 w0 = vf4[(size_t)__ldg(batch + s0) * C4 + c];
            float4 w1 = vf4[(size_t)__ldg(batch + s1) * C4 + c];
            float4 w2 = vf4[(size_t)__ldg(batch + s2) * C4 + c];
            float4 w3 = vf4[(size_t)__ldg(batch + s3) * C4 + c];
            v0.x += w0.x; v0.y += w0.y; v0.z += w0.z; v0.w += w0.w;
            v1.x += w1.x; v1.y += w1.y; v1.z += w1.z; v1.w += w1.w;
            v2.x += w2.x; v2.y += w2.y; v2.z += w2.z; v2.w += w2.w;
            v3.x += w3.x; v3.y += w3.y; v3.z += w3.z; v3.w += w3.w;
        }
        acc.x += (v0.x + v1.x) + (v2.x + v3.x);
        acc.y += (v0.y + v1.y) + (v2.y + v3.y);
        acc.z += (v0.z + v1.z) + (v2.z + v3.z);
        acc.w += (v0.w + v1.w) + (v2.w + v3.w);
    }
    for (; p < p1; p++) {
        int s = __ldg(esrc + p);
        float4 v = f4[(size_t)s * C4 + c];
        if (VIRT) {
            float4 w = vf4[(size_t)__ldg(batch + s) * C4 + c];
            v.x += w.x; v.y += w.y; v.z += w.z; v.w += w.w;
        }
        acc.x += v.x; acc.y += v.y; acc.z += v.z; acc.w += v.w;
    }
    uint2 uh, ul;
    split4(acc, uh, ul);
    reinterpret_cast<uint2*>(hi)[(size_t)n * C4 + c] = uh;
    reinterpret_cast<uint2*>(lo)[(size_t)n * C4 + c] = ul;
}

// ---------------- segmented pools over sorted batch ----------------
// pool_virt: out(split) = vf[g] + sum_{n in graph g} h[n]
__global__ void pool_virt_k(const float* __restrict__ h, const int* __restrict__ goff,
                            const float* __restrict__ vf,
                            __nv_bfloat16* __restrict__ phi, __nv_bfloat16* __restrict__ plo) {
    const int g = blockIdx.x, c = threadIdx.x;   // c: 0..127 (H/4)
    const float4* h4 = reinterpret_cast<const float4*>(h);
    float4 a0 = reinterpret_cast<const float4*>(vf)[(size_t)g * 128 + c];
    float4 a1 = make_float4(0.f, 0.f, 0.f, 0.f);
    const int n0 = __ldg(goff + g), n1 = __ldg(goff + g + 1);
    int n = n0;
    for (; n + 2 <= n1; n += 2) {
        float4 v0 = h4[(size_t)n * 128 + c];
        float4 v1 = h4[(size_t)(n + 1) * 128 + c];
        a0.x += v0.x; a0.y += v0.y; a0.z += v0.z; a0.w += v0.w;
        a1.x += v1.x; a1.y += v1.y; a1.z += v1.z; a1.w += v1.w;
    }
    if (n < n1) {
        float4 v = h4[(size_t)n * 128 + c];
        a0.x += v.x; a0.y += v.y; a0.z += v.z; a0.w += v.w;
    }
    a0.x += a1.x; a0.y += a1.y; a0.z += a1.z; a0.w += a1.w;
    uint2 uh, ul;
    split4(a0, uh, ul);
    reinterpret_cast<uint2*>(phi)[(size_t)g * 128 + c] = uh;
    reinterpret_cast<uint2*>(plo)[(size_t)g * 128 + c] = ul;
}

// mean pool readout: out[g] = sum / max(cnt,1)
__global__ void pool_mean_k(const float* __restrict__ h, const int* __restrict__ goff,
                            float* __restrict__ out) {
    const int g = blockIdx.x, c = threadIdx.x;
    const float4* h4 = reinterpret_cast<const float4*>(h);
    float4 a0 = make_float4(0.f, 0.f, 0.f, 0.f);
    float4 a1 = make_float4(0.f, 0.f, 0.f, 0.f);
    const int n0 = __ldg(goff + g), n1 = __ldg(goff + g + 1);
    int n = n0;
    for (; n + 2 <= n1; n += 2) {
        float4 v0 = h4[(size_t)n * 128 + c];
        float4 v1 = h4[(size_t)(n + 1) * 128 + c];
        a0.x += v0.x; a0.y += v0.y; a0.z += v0.z; a0.w += v0.w;
        a1.x += v1.x; a1.y += v1.y; a1.z += v1.z; a1.w += v1.w;
    }
    if (n < n1) {
        float4 v = h4[(size_t)n * 128 + c];
        a0.x += v.x; a0.y += v.y; a0.z += v.z; a0.w += v.w;
    }
    float inv = 1.0f / fmaxf((float)(n1 - n0), 1.0f);
    a0.x = (a0.x + a1.x) * inv; a0.y = (a0.y + a1.y) * inv;
    a0.z = (a0.z + a1.z) * inv; a0.w = (a0.w + a1.w) * inv;
    reinterpret_cast<float4*>(out)[(size_t)g * 128 + c] = a0;
}

__global__ void vinit_k(float* __restrict__ vf, const float* __restrict__ vemb) {
    int idx = blockIdx.x * blockDim.x + threadIdx.x;
    if (idx >= kG * kH / 4) return;
    reinterpret_cast<float4*>(vf)[idx] =
        reinterpret_cast<const float4*>(vemb)[idx & (kH / 4 - 1)];
}

// ---------------- host launcher ----------------
static void run_gemm(const __nv_bfloat16* Ahi, const __nv_bfloat16* Alo,
                     const __nv_bfloat16* Bhi, const __nv_bfloat16* Blo,
                     const float* lb, const float* ga, const float* be,
                     float* C, __nv_bfloat16* Chi, __nv_bfloat16* Clo,
                     int M, int K, int Nc, bool relu, bool split) {
    dim3 grid(Nc / 128, (M + 127) / 128);
    if (split) {
        if (relu) gemm_bf16<1,1><<<grid, 256, DSMEM>>>(Ahi, Alo, Bhi, Blo, lb, ga, be, C, Chi, Clo, M, K, Nc);
        else      gemm_bf16<0,1><<<grid, 256, DSMEM>>>(Ahi, Alo, Bhi, Blo, lb, ga, be, C, Chi, Clo, M, K, Nc);
    } else {
        if (relu) gemm_bf16<1,0><<<grid, 256, DSMEM>>>(Ahi, Alo, Bhi, Blo, lb, ga, be, C, Chi, Clo, M, K, Nc);
        else      gemm_bf16<0,0><<<grid, 256, DSMEM>>>(Ahi, Alo, Bhi, Blo, lb, ga, be, C, Chi, Clo, M, K, Nc);
    }
}

static void run_split(const float* A, __nv_bfloat16* hi, __nv_bfloat16* lo, size_t n) {
    int n4 = (int)(n / 4);
    split_k<<<(n4 + 255) / 256, 256>>>(A, hi, lo, n4);
}

extern "C" void kernel_launch(void* const* d_in, const int* in_sizes, int n_in,
                              void* d_out, int out_size) {
    const float* x      = (const float*)d_in[0];
    const int*   ei     = (const int*)  d_in[1];
    const int*   batch  = (const int*)  d_in[2];
    const float* c1_W1  = (const float*)d_in[3];
    const float* c1_b1  = (const float*)d_in[4];
    const float* c1_g1  = (const float*)d_in[5];
    const float* c1_be1 = (const float*)d_in[6];
    const float* c1_W2  = (const float*)d_in[7];
    const float* c1_b2  = (const float*)d_in[8];
    const float* bn1_g  = (const float*)d_in[9];
    const float* bn1_b  = (const float*)d_in[10];
    const float* cs_W1  = (const float*)d_in[11];
    const float* cs_b1  = (const float*)d_in[12];
    const float* cs_g1  = (const float*)d_in[13];
    const float* cs_be1 = (const float*)d_in[14];
    const float* cs_W2  = (const float*)d_in[15];
    const float* cs_b2  = (const float*)d_in[16];
    const float* bns_g  = (const float*)d_in[17];
    const float* bns_b  = (const float*)d_in[18];
    const float* vemb   = (const float*)d_in[19];
    const float* v_W1   = (const float*)d_in[20];
    const float* v_b1   = (const float*)d_in[21];
    const float* v_g1   = (const float*)d_in[22];
    const float* v_be1  = (const float*)d_in[23];
    const float* v_W2   = (const float*)d_in[24];
    const float* v_b2   = (const float*)d_in[25];
    const float* v_g2   = (const float*)d_in[26];
    const float* v_be2  = (const float*)d_in[27];

    cudaFuncSetAttribute(gemm_bf16<0,0>, cudaFuncAttributeMaxDynamicSharedMemorySize, DSMEM);
    cudaFuncSetAttribute(gemm_bf16<0,1>, cudaFuncAttributeMaxDynamicSharedMemorySize, DSMEM);
    cudaFuncSetAttribute(gemm_bf16<1,0>, cudaFuncAttributeMaxDynamicSharedMemorySize, DSMEM);
    cudaFuncSetAttribute(gemm_bf16<1,1>, cudaFuncAttributeMaxDynamicSharedMemorySize, DSMEM);

    float *h, *vf;
    int *cnt, *goff, *deg, *cur, *rowptr, *esrc;
    __nv_bfloat16 *wthi, *wtlo, *ahi, *alo, *bhi, *blo, *phi, *plo, *qhi, *qlo;
    cudaGetSymbolAddress((void**)&h,      g_h);
    cudaGetSymbolAddress((void**)&vf,     g_vf);
    cudaGetSymbolAddress((void**)&cnt,    g_cnt);
    cudaGetSymbolAddress((void**)&goff,   g_goff);
    cudaGetSymbolAddress((void**)&deg,    g_deg);
    cudaGetSymbolAddress((void**)&cur,    g_cur);
    cudaGetSymbolAddress((void**)&rowptr, g_rowptr);
    cudaGetSymbolAddress((void**)&esrc,   g_esrc);
    cudaGetSymbolAddress((void**)&wthi,   g_wthi);
    cudaGetSymbolAddress((void**)&wtlo,   g_wtlo);
    cudaGetSymbolAddress((void**)&ahi,    g_ahi);
    cudaGetSymbolAddress((void**)&alo,    g_alo);
    cudaGetSymbolAddress((void**)&bhi,    g_bhi);
    cudaGetSymbolAddress((void**)&blo,    g_blo);
    cudaGetSymbolAddress((void**)&phi,    g_phi);
    cudaGetSymbolAddress((void**)&plo,    g_plo);
    cudaGetSymbolAddress((void**)&qhi,    g_qhi);
    cudaGetSymbolAddress((void**)&qlo,    g_qlo);

    const int* srcI = ei;
    const int* dstI = ei + kE;

    // ---- CSR + graph-range build ----
    cudaMemsetAsync(deg, 0, kN * sizeof(int));
    cudaMemsetAsync(cur, 0, kN * sizeof(int));
    cudaMemsetAsync(cnt, 0, kG * sizeof(int));
    degcount_k<<<(kE + 255) / 256, 256>>>(dstI, deg);
    count_k<<<(kN + 255) / 256, 256>>>(batch, cnt);
    scan_k<<<1, 1024>>>(deg, rowptr);
    gscan_k<<<1, 32>>>(cnt, goff);
    fill_k<<<(kE + 255) / 256, 256>>>(srcI, dstI, rowptr, cur, esrc);

    // ---- weight splits ----
    run_split(c1_W1, wthi + OFF_c1W1, wtlo + OFF_c1W1, (size_t)kD * kH2);
    run_split(c1_W2, wthi + OFF_c1W2, wtlo + OFF_c1W2, (size_t)kH2 * kH);
    for (int i = 0; i < kL; i++) {
        run_split(cs_W1 + (size_t)i * kH * kH2,
                  wthi + OFF_csW1 + (size_t)i * kH * kH2,
                  wtlo + OFF_csW1 + (size_t)i * kH * kH2, (size_t)kH * kH2);
        run_split(cs_W2 + (size_t)i * kH2 * kH,
                  wthi + OFF_csW2 + (size_t)i * kH2 * kH,
                  wtlo + OFF_csW2 + (size_t)i * kH2 * kH, (size_t)kH2 * kH);
    }
    run_split(v_W1, wthi + OFF_vW1, wtlo + OFF_vW1, (size_t)kH * kH2);
    run_split(v_W2, wthi + OFF_vW2, wtlo + OFF_vW2, (size_t)kH2 * kH);

    // virtual node features
    vinit_k<<<(kG * kH / 4 + 255) / 256, 256>>>(vf, vemb);

    // ---- conv1: agg(x) -> split; MLP 128 -> 1024 -> 512 ----
    aggregate_k<kD,0><<<kN / 8, 256>>>(x, nullptr, nullptr, rowptr, esrc, ahi, alo);
    run_gemm(ahi, alo, wthi + OFF_c1W1, wtlo + OFF_c1W1, c1_b1, c1_g1, c1_be1,
             nullptr, bhi, blo, kN, kD, kH2, true, true);
    run_gemm(bhi, blo, wthi + OFF_c1W2, wtlo + OFF_c1W2, c1_b2, bn1_g, bn1_b,
             h, nullptr, nullptr, kN, kH2, kH, true, false);

    // ---- L GIN layers with virtual node ----
    for (int i = 0; i < kL; i++) {
        aggregate_k<kH,1><<<kN / 2, 256>>>(h, vf, batch, rowptr, esrc, ahi, alo);
        run_gemm(ahi, alo, wthi + OFF_csW1 + (size_t)i * kH * kH2,
                 wtlo + OFF_csW1 + (size_t)i * kH * kH2,
                 cs_b1 + i * kH2, cs_g1 + i * kH2, cs_be1 + i * kH2,
                 nullptr, bhi, blo, kN, kH, kH2, true, true);
        run_gemm(bhi, blo, wthi + OFF_csW2 + (size_t)i * kH2 * kH,
                 wtlo + OFF_csW2 + (size_t)i * kH2 * kH,
                 cs_b2 + i * kH, bns_g + i * kH, bns_b + i * kH,
                 h, nullptr, nullptr, kN, kH2, kH, i < kL - 1, false);
        if (i < kL - 1) {
            pool_virt_k<<<kG, 128>>>(h, goff, vf, phi, plo);
            run_gemm(phi, plo, wthi + OFF_vW1, wtlo + OFF_vW1, v_b1, v_g1, v_be1,
                     nullptr, qhi, qlo, kG, kH, kH2, true, true);
            run_gemm(qhi, qlo, wthi + OFF_vW2, wtlo + OFF_vW2, v_b2, v_g2, v_be2,
                     vf, nullptr, nullptr, kG, kH2, kH, true, false);
        }
    }

    // ---- mean-pool readout into d_out ----
    pool_mean_k<<<kG, 128>>>(h, goff, (float*)d_out);
}